// round 1
// baseline (speedup 1.0000x reference)
#include <cuda_runtime.h>
#include <math.h>
#include <stdint.h>

// ---------------- problem constants ----------------
#define Bb   64
#define Nn   197
#define Dd   768
#define Hh   12
#define HD   64
#define MLPD 3072
#define ROWS (Bb*Nn)          // 12608
#define NN2  (Nn*Nn)          // 38809

// ---------------- scratch (static device globals; no allocation) ----------------
__device__ float g_h [ (size_t)ROWS * Dd ];
__device__ float g_q [ (size_t)Bb * Hh * Nn * HD ];
__device__ float g_k [ (size_t)Bb * Hh * Nn * HD ];
__device__ float g_v [ (size_t)Bb * Hh * Nn * HD ];
__device__ float g_attn [ (size_t)Bb * Hh * NN2 ];
__device__ float g_y [ (size_t)ROWS * Dd ];
__device__ float g_x1[ (size_t)ROWS * Dd ];
__device__ float g_m [ (size_t)ROWS * MLPD ];

// ---------------- LayerNorm + SSF ----------------
__global__ __launch_bounds__(256) void ln_ssf_kernel(
    const float* __restrict__ x, const float* __restrict__ w, const float* __restrict__ b,
    const float* __restrict__ sc, const float* __restrict__ sh, float* __restrict__ out)
{
    int row = blockIdx.x;
    const float* xr = x + (size_t)row * Dd;
    float* orow = out + (size_t)row * Dd;
    int tid = threadIdx.x;
    float v0 = xr[tid], v1 = xr[tid + 256], v2 = xr[tid + 512];
    float s = v0 + v1 + v2;
    __shared__ float red[8];
    int lane = tid & 31, wp = tid >> 5;
    #pragma unroll
    for (int o = 16; o; o >>= 1) s += __shfl_xor_sync(~0u, s, o);
    if (!lane) red[wp] = s;
    __syncthreads();
    float tot = red[0]+red[1]+red[2]+red[3]+red[4]+red[5]+red[6]+red[7];
    float mean = tot * (1.f / 768.f);
    float d0 = v0 - mean, d1 = v1 - mean, d2 = v2 - mean;
    float vs = d0*d0 + d1*d1 + d2*d2;
    #pragma unroll
    for (int o = 16; o; o >>= 1) vs += __shfl_xor_sync(~0u, vs, o);
    __syncthreads();
    if (!lane) red[wp] = vs;
    __syncthreads();
    float var = (red[0]+red[1]+red[2]+red[3]+red[4]+red[5]+red[6]+red[7]) * (1.f / 768.f);
    float inv = rsqrtf(var + 1e-5f);
    orow[tid]       = (d0*inv*w[tid]       + b[tid])       * sc[tid]       + sh[tid];
    orow[tid + 256] = (d1*inv*w[tid + 256] + b[tid + 256]) * sc[tid + 256] + sh[tid + 256];
    orow[tid + 512] = (d2*inv*w[tid + 512] + b[tid + 512]) * sc[tid + 512] + sh[tid + 512];
}

// ---------------- tiled fp32 NT GEMM:  C[M,N] = A[M,K] * B[N,K]^T  ----------------
struct EpiP {
    const float* bias;
    const float* scale;
    const float* shift;
    const float* resid;
    const float* gamma;
    float* out;
    float* outk;
    float* outv;
    const float* qb;
    const float* vb;
};

// EPI: 0 = qkv scatter, 1 = proj(+resid,gamma), 2 = gelu, 3 = fc2(+resid,gamma)
template<int EPI>
__global__ __launch_bounds__(256) void gemm_nt(
    const float* __restrict__ A, const float* __restrict__ Bw,
    int M, int N, int K, EpiP p)
{
    __shared__ float As[8][128];
    __shared__ float Bs[8][128];
    int tid = threadIdx.x;
    int row0 = blockIdx.y * 128, col0 = blockIdx.x * 128;
    int tr = tid >> 4, tc = tid & 15;
    int la_r = tid >> 1;
    int la_c = (tid & 1) * 4;
    float acc[8][8];
    #pragma unroll
    for (int i = 0; i < 8; i++)
        #pragma unroll
        for (int j = 0; j < 8; j++) acc[i][j] = 0.f;

    for (int k0 = 0; k0 < K; k0 += 8) {
        int ar = row0 + la_r;
        float4 av = make_float4(0.f, 0.f, 0.f, 0.f);
        if (ar < M) av = *(const float4*)(A + (size_t)ar * K + k0 + la_c);
        As[la_c + 0][la_r] = av.x; As[la_c + 1][la_r] = av.y;
        As[la_c + 2][la_r] = av.z; As[la_c + 3][la_r] = av.w;
        float4 bv = *(const float4*)(Bw + (size_t)(col0 + la_r) * K + k0 + la_c);
        Bs[la_c + 0][la_r] = bv.x; Bs[la_c + 1][la_r] = bv.y;
        Bs[la_c + 2][la_r] = bv.z; Bs[la_c + 3][la_r] = bv.w;
        __syncthreads();
        #pragma unroll
        for (int kk = 0; kk < 8; ++kk) {
            float4 a0 = *(const float4*)&As[kk][tr * 8];
            float4 a1 = *(const float4*)&As[kk][tr * 8 + 4];
            float4 b0 = *(const float4*)&Bs[kk][tc * 8];
            float4 b1 = *(const float4*)&Bs[kk][tc * 8 + 4];
            float ra[8] = {a0.x, a0.y, a0.z, a0.w, a1.x, a1.y, a1.z, a1.w};
            float rb[8] = {b0.x, b0.y, b0.z, b0.w, b1.x, b1.y, b1.z, b1.w};
            #pragma unroll
            for (int i = 0; i < 8; i++)
                #pragma unroll
                for (int j = 0; j < 8; j++)
                    acc[i][j] = fmaf(ra[i], rb[j], acc[i][j]);
        }
        __syncthreads();
    }

    #pragma unroll
    for (int i = 0; i < 8; i++) {
        int r = row0 + tr * 8 + i;
        if (r >= M) break;
        #pragma unroll
        for (int j = 0; j < 8; j++) {
            int c = col0 + tc * 8 + j;
            float a = acc[i][j];
            if constexpr (EPI == 0) {
                int part = c / Dd;
                int rr = c - part * Dd;
                float bias = (part == 0) ? p.qb[rr] : (part == 2 ? p.vb[rr] : 0.f);
                float val = (a + bias) * p.scale[c] + p.shift[c];
                int b_ = r / Nn, n_ = r - b_ * Nn;
                int hh = rr >> 6, d = rr & 63;
                size_t idx = ((((size_t)b_ * Hh + hh) * Nn) + n_) * HD + d;
                if (part == 0)      p.out [idx] = val * 0.125f;
                else if (part == 1) p.outk[idx] = val;
                else                p.outv[idx] = val;
            } else if constexpr (EPI == 1 || EPI == 3) {
                float val = (a + p.bias[c]) * p.scale[c] + p.shift[c];
                size_t idx = (size_t)r * N + c;
                p.out[idx] = p.resid[idx] + p.gamma[c] * val;
            } else { // GELU
                float v = a + p.bias[c];
                size_t idx = (size_t)r * N + c;
                p.out[idx] = 0.5f * v * (1.f + erff(v * 0.70710678118654752f));
            }
        }
    }
}

// ---------------- attention scores + softmax (block per (b,h)) ----------------
__global__ __launch_bounds__(256) void attn_scores_kernel(
    const float* __restrict__ q, const float* __restrict__ k,
    const float* __restrict__ table, const int* __restrict__ relidx,
    float* __restrict__ attn)
{
    extern __shared__ float smem[];
    float* ks = smem;                 // 197*65
    float* qrow = smem + 197 * 65;    // 8*64
    int bh = blockIdx.x;
    int h = bh % Hh;
    const float* kbase = k + (size_t)bh * Nn * HD;
    for (int i = threadIdx.x; i < Nn * HD; i += blockDim.x)
        ks[(i >> 6) * 65 + (i & 63)] = kbase[i];
    __syncthreads();

    int w = threadIdx.x >> 5, lane = threadIdx.x & 31;
    const float* qbase = q + (size_t)bh * Nn * HD;
    float* abase = attn + (size_t)bh * NN2;
    float* qs = qrow + w * 64;

    for (int n = w; n < Nn; n += 8) {
        qs[lane]      = qbase[n * 64 + lane];
        qs[lane + 32] = qbase[n * 64 + lane + 32];
        __syncwarp();
        float sc[7];
        int cnt = 0;
        float mx = -1e30f;
        for (int m = lane; m < Nn; m += 32) {
            float s = 0.f;
            const float* kr = &ks[m * 65];
            #pragma unroll
            for (int d = 0; d < 64; d++) s = fmaf(qs[d], kr[d], s);
            s += table[relidx[n * Nn + m] * Hh + h];
            sc[cnt++] = s;
            mx = fmaxf(mx, s);
        }
        #pragma unroll
        for (int o = 16; o; o >>= 1) mx = fmaxf(mx, __shfl_xor_sync(~0u, mx, o));
        float sum = 0.f;
        for (int i = 0; i < cnt; i++) { sc[i] = __expf(sc[i] - mx); sum += sc[i]; }
        #pragma unroll
        for (int o = 16; o; o >>= 1) sum += __shfl_xor_sync(~0u, sum, o);
        float inv = 1.f / sum;
        cnt = 0;
        for (int m = lane; m < Nn; m += 32) abase[n * Nn + m] = sc[cnt++] * inv;
        __syncwarp();
    }
}

// ---------------- DCF head mix + attn @ V (block per (b,n)) ----------------
__global__ __launch_bounds__(256) void mix_av_kernel(
    const float* __restrict__ attn, const float* __restrict__ v,
    const float* __restrict__ bases, float* __restrict__ y)
{
    __shared__ float a_s[Hh][Nn];
    __shared__ float m_s[Hh][200];
    __shared__ float c_s[Hh][Hh];
    int bn = blockIdx.x;
    int b = bn / Nn, n = bn - b * Nn;
    int tid = threadIdx.x;
    if (tid < 144) {
        int kk = tid / 12, hh = tid % 12;
        c_s[hh][kk] = bases[kk * Hh + hh] + (hh == kk ? 1.f : 0.f);
    }
    for (int i = tid; i < Hh * Nn; i += 256) {
        int hh = i / Nn, l = i - hh * Nn;
        a_s[hh][l] = attn[(((size_t)b * Hh + hh) * Nn + n) * Nn + l];
    }
    __syncthreads();
    for (int i = tid; i < Hh * Nn; i += 256) {
        int kk = i / Nn, l = i - kk * Nn;
        float s = 0.f;
        #pragma unroll
        for (int hh = 0; hh < Hh; hh++) s = fmaf(a_s[hh][l], c_s[hh][kk], s);
        m_s[kk][l] = s;
    }
    __syncthreads();
    for (int j = tid; j < Dd; j += 256) {
        int kk = j >> 6, d = j & 63;
        const float* vp = v + (((size_t)b * Hh + kk) * Nn) * HD + d;
        const float* mr = m_s[kk];
        float s = 0.f;
        #pragma unroll 4
        for (int l = 0; l < Nn; l++) s = fmaf(mr[l], vp[(size_t)l * HD], s);
        y[(size_t)bn * Dd + j] = s;
    }
}

// ---------------- launcher ----------------
extern "C" void kernel_launch(void* const* d_in, const int* in_sizes, int n_in,
                              void* d_out, int out_size)
{
    const float* x             = (const float*)d_in[0];
    const float* w_qkv         = (const float*)d_in[1];
    const float* q_bias        = (const float*)d_in[2];
    const float* v_bias        = (const float*)d_in[3];
    const float* ssf_scale_qkv = (const float*)d_in[4];
    const float* ssf_shift_qkv = (const float*)d_in[5];
    const float* rel_table     = (const float*)d_in[6];
    const float* bases_coeff   = (const float*)d_in[7];
    const float* w_proj        = (const float*)d_in[8];
    const float* b_proj        = (const float*)d_in[9];
    const float* ssf_scale_pr  = (const float*)d_in[10];
    const float* ssf_shift_pr  = (const float*)d_in[11];
    const float* norm1_w       = (const float*)d_in[12];
    const float* norm1_b       = (const float*)d_in[13];
    const float* norm2_w       = (const float*)d_in[14];
    const float* norm2_b       = (const float*)d_in[15];
    const float* ssf_scale_1   = (const float*)d_in[16];
    const float* ssf_shift_1   = (const float*)d_in[17];
    const float* ssf_scale_2   = (const float*)d_in[18];
    const float* ssf_shift_2   = (const float*)d_in[19];
    const float* w_fc1         = (const float*)d_in[20];
    const float* b_fc1         = (const float*)d_in[21];
    const float* w_fc2         = (const float*)d_in[22];
    const float* b_fc2         = (const float*)d_in[23];
    const float* ssf_scale_mlp = (const float*)d_in[24];
    const float* ssf_shift_mlp = (const float*)d_in[25];
    const float* gamma_1       = (const float*)d_in[26];
    const float* gamma_2       = (const float*)d_in[27];
    const int*   rel_pos_index = (const int*)d_in[28];
    float* out = (float*)d_out;

    float *ph, *pq, *pk, *pv, *pattn, *py, *px1, *pm;
    cudaGetSymbolAddress((void**)&ph,    g_h);
    cudaGetSymbolAddress((void**)&pq,    g_q);
    cudaGetSymbolAddress((void**)&pk,    g_k);
    cudaGetSymbolAddress((void**)&pv,    g_v);
    cudaGetSymbolAddress((void**)&pattn, g_attn);
    cudaGetSymbolAddress((void**)&py,    g_y);
    cudaGetSymbolAddress((void**)&px1,   g_x1);
    cudaGetSymbolAddress((void**)&pm,    g_m);

    // 1. LN1 + SSF
    ln_ssf_kernel<<<ROWS, 256>>>(x, norm1_w, norm1_b, ssf_scale_1, ssf_shift_1, ph);

    // 2. QKV GEMM + bias + SSF + scatter
    {
        EpiP p = {};
        p.scale = ssf_scale_qkv; p.shift = ssf_shift_qkv;
        p.out = pq; p.outk = pk; p.outv = pv;
        p.qb = q_bias; p.vb = v_bias;
        dim3 grid(3 * Dd / 128, (ROWS + 127) / 128);
        gemm_nt<0><<<grid, 256>>>(ph, w_qkv, ROWS, 3 * Dd, Dd, p);
    }

    // 3. attention scores + rel bias + softmax
    {
        int smem = (197 * 65 + 8 * 64) * sizeof(float);
        cudaFuncSetAttribute(attn_scores_kernel,
                             cudaFuncAttributeMaxDynamicSharedMemorySize, smem);
        attn_scores_kernel<<<Bb * Hh, 256, smem>>>(pq, pk, rel_table, rel_pos_index, pattn);
    }

    // 4. DCF head mix + attn@V
    mix_av_kernel<<<ROWS, 256>>>(pattn, pv, bases_coeff, py);

    // 5. proj GEMM + SSF + gamma1 residual
    {
        EpiP p = {};
        p.bias = b_proj; p.scale = ssf_scale_pr; p.shift = ssf_shift_pr;
        p.resid = x; p.gamma = gamma_1; p.out = px1;
        dim3 grid(Dd / 128, (ROWS + 127) / 128);
        gemm_nt<1><<<grid, 256>>>(py, w_proj, ROWS, Dd, Dd, p);
    }

    // 6. LN2 + SSF
    ln_ssf_kernel<<<ROWS, 256>>>(px1, norm2_w, norm2_b, ssf_scale_2, ssf_shift_2, ph);

    // 7. fc1 GEMM + GELU
    {
        EpiP p = {};
        p.bias = b_fc1; p.out = pm;
        dim3 grid(MLPD / 128, (ROWS + 127) / 128);
        gemm_nt<2><<<grid, 256>>>(ph, w_fc1, ROWS, MLPD, Dd, p);
    }

    // 8. fc2 GEMM + SSF + gamma2 residual -> out
    {
        EpiP p = {};
        p.bias = b_fc2; p.scale = ssf_scale_mlp; p.shift = ssf_shift_mlp;
        p.resid = px1; p.gamma = gamma_2; p.out = out;
        dim3 grid(Dd / 128, (ROWS + 127) / 128);
        gemm_nt<3><<<grid, 256>>>(pm, w_fc2, ROWS, Dd, MLPD, p);
    }
}

// round 4
// speedup vs baseline: 1.6211x; 1.6211x over previous
#include <cuda_runtime.h>
#include <math.h>
#include <stdint.h>

// ---------------- problem constants ----------------
#define Bb   64
#define Nn   197
#define Dd   768
#define Hh   12
#define HD   64
#define MLPD 3072
#define ROWS (Bb*Nn)          // 12608
#define NN2  (Nn*Nn)          // 38809

// ---------------- scratch (static device globals; no allocation) ----------------
__device__ float g_h [ (size_t)ROWS * Dd ];
__device__ float g_q [ (size_t)Bb * Hh * Nn * HD ];
__device__ float g_k [ (size_t)Bb * Hh * Nn * HD ];
__device__ float g_v [ (size_t)Bb * Hh * Nn * HD ];
__device__ float g_attn [ (size_t)Bb * Hh * NN2 ];
__device__ float g_y [ (size_t)ROWS * Dd ];
__device__ float g_x1[ (size_t)ROWS * Dd ];
__device__ float g_m [ (size_t)ROWS * MLPD ];
// tf32-rounded weight copies
__device__ float g_wq[ (size_t)3 * Dd * Dd ];
__device__ float g_wp[ (size_t)Dd * Dd ];
__device__ float g_w1[ (size_t)MLPD * Dd ];
__device__ float g_w2[ (size_t)Dd * MLPD ];

// ---------------- PTX helpers ----------------
__device__ __forceinline__ uint32_t smem_u32(const void* p) {
    uint32_t a;
    asm("{ .reg .u64 t; cvta.to.shared.u64 t, %1; cvt.u32.u64 %0, t; }" : "=r"(a) : "l"(p));
    return a;
}
__device__ __forceinline__ float to_tf32(float x) {
    uint32_t o;
    asm("cvt.rna.tf32.f32 %0, %1;" : "=r"(o) : "f"(x));
    return __uint_as_float(o);
}
__device__ __forceinline__ void cp16(uint32_t dst, const void* src) {
    asm volatile("cp.async.cg.shared.global [%0], [%1], 16;" :: "r"(dst), "l"(src));
}
__device__ __forceinline__ void sts_zero16(uint32_t dst) {
    asm volatile("st.shared.v4.b32 [%0], {%1,%1,%1,%1};" :: "r"(dst), "r"(0u));
}
__device__ __forceinline__ void cp_commit() { asm volatile("cp.async.commit_group;" ::: "memory"); }
template<int N>
__device__ __forceinline__ void cp_wait() { asm volatile("cp.async.wait_group %0;" :: "n"(N) : "memory"); }

// tf32 warp MMA: D(16x8) += A(16x8) * B(8x8)   [row.col]
__device__ __forceinline__ void mma_tf32(float* c, const uint32_t* a, const uint32_t* b) {
    asm volatile(
        "mma.sync.aligned.m16n8k8.row.col.f32.tf32.tf32.f32 "
        "{%0,%1,%2,%3}, {%4,%5,%6,%7}, {%8,%9}, {%0,%1,%2,%3};"
        : "+f"(c[0]), "+f"(c[1]), "+f"(c[2]), "+f"(c[3])
        : "r"(a[0]), "r"(a[1]), "r"(a[2]), "r"(a[3]), "r"(b[0]), "r"(b[1]));
}

// ---------------- epilogue params ----------------
struct EpiP {
    const float* bias;
    const float* scale;
    const float* shift;
    const float* resid;
    const float* gamma;
    float* out;
    float* outk;
    float* outv;
    const float* qb;
    const float* vb;
};

// per-element epilogue
template<int EPI>
__device__ __forceinline__ void epi_store(int r, int c, float a, int N_, const EpiP& p) {
    if constexpr (EPI == 0) {
        int part = c / Dd;
        int rr = c - part * Dd;
        float bias = (part == 0) ? p.qb[rr] : (part == 2 ? p.vb[rr] : 0.f);
        float val = (a + bias) * p.scale[c] + p.shift[c];
        int b_ = r / Nn, n_ = r - b_ * Nn;
        int hh = rr >> 6, d = rr & 63;
        size_t idx = ((((size_t)b_ * Hh + hh) * Nn) + n_) * HD + d;
        if (part == 0)      p.out [idx] = val * 0.125f;
        else if (part == 1) p.outk[idx] = val;
        else                p.outv[idx] = val;
    } else if constexpr (EPI == 1 || EPI == 3) {
        float val = (a + p.bias[c]) * p.scale[c] + p.shift[c];
        size_t idx = (size_t)r * N_ + c;
        p.out[idx] = p.resid[idx] + p.gamma[c] * val;
    } else { // GELU (tf32-rounded: feeds fc2 GEMM)
        float v = a + p.bias[c];
        size_t idx = (size_t)r * N_ + c;
        p.out[idx] = to_tf32(0.5f * v * (1.f + erff(v * 0.70710678118654752f)));
    }
}

// ---------------- mma.sync tf32 GEMM:  C[M,N_] = A[M,K] * B[N_,K]^T ----------------
// 128x128 block tile, 8 warps (2x4), warp tile 64x32, K-slab 32, 3-stage cp.async.
#define PSTRIDE 36                       // padded floats per smem row
#define SLABF   (2 * 128 * PSTRIDE)      // floats per stage (A+B)
#define GSTAGES 3
#define GEMM_SMEM (GSTAGES * SLABF * 4)  // 110592 B

template<int EPI>
__global__ __launch_bounds__(256, 1) void gemm_mma(
    const float* __restrict__ A, const float* __restrict__ Bw,
    int M, int N_, int K, EpiP p)
{
    extern __shared__ float sm[];
    int tid = threadIdx.x;
    int row0 = blockIdx.y << 7, col0 = blockIdx.x << 7;
    int warp = tid >> 5, lane = tid & 31;
    int wm = warp >> 2, wn = warp & 3;           // 2x4 warp grid
    int g = lane >> 2, t = lane & 3;             // fragment coords

    // ---- loader assignment: threads 0..127 -> A rows, 128..255 -> B rows ----
    bool isB = tid >= 128;
    int lr = tid & 127;
    const float* gsrc = isB ? (Bw + (size_t)(col0 + lr) * K)
                            : (A  + (size_t)(row0 + lr) * K);
    bool lvalid = isB ? true : (row0 + lr < M);
    uint32_t sdst = smem_u32(sm) + (uint32_t)((isB ? 128 * PSTRIDE : 0) + lr * PSTRIDE) * 4u;

    auto load_slab = [&](int slab, int stage) {
        uint32_t dst = sdst + (uint32_t)stage * (SLABF * 4u);
        const float* src = gsrc + slab * 32;
        if (lvalid) {
            #pragma unroll
            for (int j = 0; j < 8; j++) cp16(dst + j * 16, src + j * 4);
        } else {
            #pragma unroll
            for (int j = 0; j < 8; j++) sts_zero16(dst + j * 16);
        }
    };

    float c[4][4][4];
    #pragma unroll
    for (int i = 0; i < 4; i++)
        #pragma unroll
        for (int j = 0; j < 4; j++)
            { c[i][j][0] = 0.f; c[i][j][1] = 0.f; c[i][j][2] = 0.f; c[i][j][3] = 0.f; }

    const int nslab = K >> 5;
    load_slab(0, 0); cp_commit();
    if (nslab > 1) load_slab(1, 1);
    cp_commit();

    for (int s = 0; s < nslab; s++) {
        cp_wait<1>();          // slab s resident (group committed 2 iters ago)
        __syncthreads();       // all warps see it; stage (s+2)%3 free of readers
        if (s + 2 < nslab) load_slab(s + 2, (s + 2) % GSTAGES);
        cp_commit();

        const float* As = sm + (s % GSTAGES) * SLABF + wm * 64 * PSTRIDE;
        const float* Bs = sm + (s % GSTAGES) * SLABF + 128 * PSTRIDE + wn * 32 * PSTRIDE;

        #pragma unroll
        for (int kk = 0; kk < 4; kk++) {
            int kc = kk * 8 + t;
            uint32_t af[4][4];
            #pragma unroll
            for (int mt = 0; mt < 4; mt++) {
                const float* ap = As + mt * 16 * PSTRIDE;
                af[mt][0] = __float_as_uint(ap[ g      * PSTRIDE + kc]);
                af[mt][1] = __float_as_uint(ap[(g + 8) * PSTRIDE + kc]);
                af[mt][2] = __float_as_uint(ap[ g      * PSTRIDE + kc + 4]);
                af[mt][3] = __float_as_uint(ap[(g + 8) * PSTRIDE + kc + 4]);
            }
            uint32_t bf[4][2];
            #pragma unroll
            for (int nt = 0; nt < 4; nt++) {
                const float* bp = Bs + (nt * 8 + g) * PSTRIDE;
                bf[nt][0] = __float_as_uint(bp[kc]);
                bf[nt][1] = __float_as_uint(bp[kc + 4]);
            }
            #pragma unroll
            for (int mt = 0; mt < 4; mt++)
                #pragma unroll
                for (int nt = 0; nt < 4; nt++)
                    mma_tf32(c[mt][nt], af[mt], bf[nt]);
        }
    }
    // drain remaining (possibly empty) groups before reusing smem next launch
    cp_wait<0>();

    // ---- epilogue ----
    #pragma unroll
    for (int mt = 0; mt < 4; mt++) {
        int r_lo = row0 + wm * 64 + mt * 16 + g;
        int r_hi = r_lo + 8;
        #pragma unroll
        for (int nt = 0; nt < 4; nt++) {
            int cc = col0 + wn * 32 + nt * 8 + t * 2;
            if (r_lo < M) {
                epi_store<EPI>(r_lo, cc,     c[mt][nt][0], N_, p);
                epi_store<EPI>(r_lo, cc + 1, c[mt][nt][1], N_, p);
            }
            if (r_hi < M) {
                epi_store<EPI>(r_hi, cc,     c[mt][nt][2], N_, p);
                epi_store<EPI>(r_hi, cc + 1, c[mt][nt][3], N_, p);
            }
        }
    }
}

// ---------------- rna weight conversion ----------------
__global__ __launch_bounds__(256) void rna_kernel(const float* __restrict__ in,
                                                  float* __restrict__ out, int n4)
{
    int i = blockIdx.x * 256 + threadIdx.x;
    if (i < n4) {
        float4 v = ((const float4*)in)[i];
        v.x = to_tf32(v.x); v.y = to_tf32(v.y); v.z = to_tf32(v.z); v.w = to_tf32(v.w);
        ((float4*)out)[i] = v;
    }
}

// ---------------- LayerNorm + SSF (output rounded to tf32: feeds GEMM) ----------------
__global__ __launch_bounds__(256) void ln_ssf_kernel(
    const float* __restrict__ x, const float* __restrict__ w, const float* __restrict__ b,
    const float* __restrict__ sc, const float* __restrict__ sh, float* __restrict__ out)
{
    int row = blockIdx.x;
    const float* xr = x + (size_t)row * Dd;
    float* orow = out + (size_t)row * Dd;
    int tid = threadIdx.x;
    float v0 = xr[tid], v1 = xr[tid + 256], v2 = xr[tid + 512];
    float s = v0 + v1 + v2;
    __shared__ float red[8];
    int lane = tid & 31, wp = tid >> 5;
    #pragma unroll
    for (int o = 16; o; o >>= 1) s += __shfl_xor_sync(~0u, s, o);
    if (!lane) red[wp] = s;
    __syncthreads();
    float tot = red[0]+red[1]+red[2]+red[3]+red[4]+red[5]+red[6]+red[7];
    float mean = tot * (1.f / 768.f);
    float d0 = v0 - mean, d1 = v1 - mean, d2 = v2 - mean;
    float vs = d0*d0 + d1*d1 + d2*d2;
    #pragma unroll
    for (int o = 16; o; o >>= 1) vs += __shfl_xor_sync(~0u, vs, o);
    __syncthreads();
    if (!lane) red[wp] = vs;
    __syncthreads();
    float var = (red[0]+red[1]+red[2]+red[3]+red[4]+red[5]+red[6]+red[7]) * (1.f / 768.f);
    float inv = rsqrtf(var + 1e-5f);
    orow[tid]       = to_tf32((d0*inv*w[tid]       + b[tid])       * sc[tid]       + sh[tid]);
    orow[tid + 256] = to_tf32((d1*inv*w[tid + 256] + b[tid + 256]) * sc[tid + 256] + sh[tid + 256]);
    orow[tid + 512] = to_tf32((d2*inv*w[tid + 512] + b[tid + 512]) * sc[tid + 512] + sh[tid + 512]);
}

// ---------------- attention scores + softmax (block per (b,h)) ----------------
__global__ __launch_bounds__(256) void attn_scores_kernel(
    const float* __restrict__ q, const float* __restrict__ k,
    const float* __restrict__ table, const int* __restrict__ relidx,
    float* __restrict__ attn)
{
    extern __shared__ float smem[];
    float* ks = smem;                 // 197*65
    float* qrow = smem + 197 * 65;    // 8*64
    int bh = blockIdx.x;
    int h = bh % Hh;
    const float* kbase = k + (size_t)bh * Nn * HD;
    for (int i = threadIdx.x; i < Nn * HD; i += blockDim.x)
        ks[(i >> 6) * 65 + (i & 63)] = kbase[i];
    __syncthreads();

    int w = threadIdx.x >> 5, lane = threadIdx.x & 31;
    const float* qbase = q + (size_t)bh * Nn * HD;
    float* abase = attn + (size_t)bh * NN2;
    float* qs = qrow + w * 64;

    for (int n = w; n < Nn; n += 8) {
        qs[lane]      = qbase[n * 64 + lane];
        qs[lane + 32] = qbase[n * 64 + lane + 32];
        __syncwarp();
        float sc[7];
        int cnt = 0;
        float mx = -1e30f;
        for (int m = lane; m < Nn; m += 32) {
            float s = 0.f;
            const float* kr = &ks[m * 65];
            #pragma unroll
            for (int d = 0; d < 64; d++) s = fmaf(qs[d], kr[d], s);
            s += table[relidx[n * Nn + m] * Hh + h];
            sc[cnt++] = s;
            mx = fmaxf(mx, s);
        }
        #pragma unroll
        for (int o = 16; o; o >>= 1) mx = fmaxf(mx, __shfl_xor_sync(~0u, mx, o));
        float sum = 0.f;
        for (int i = 0; i < cnt; i++) { sc[i] = __expf(sc[i] - mx); sum += sc[i]; }
        #pragma unroll
        for (int o = 16; o; o >>= 1) sum += __shfl_xor_sync(~0u, sum, o);
        float inv = 1.f / sum;
        cnt = 0;
        for (int m = lane; m < Nn; m += 32) abase[n * Nn + m] = sc[cnt++] * inv;
        __syncwarp();
    }
}

// ---------------- DCF head mix + attn @ V (block per (b,n)); output tf32-rounded ----------------
__global__ __launch_bounds__(256) void mix_av_kernel(
    const float* __restrict__ attn, const float* __restrict__ v,
    const float* __restrict__ bases, float* __restrict__ y)
{
    __shared__ float a_s[Hh][Nn];
    __shared__ float m_s[Hh][200];
    __shared__ float c_s[Hh][Hh];
    int bn = blockIdx.x;
    int b = bn / Nn, n = bn - b * Nn;
    int tid = threadIdx.x;
    if (tid < 144) {
        int kk = tid / 12, hh = tid % 12;
        c_s[hh][kk] = bases[kk * Hh + hh] + (hh == kk ? 1.f : 0.f);
    }
    for (int i = tid; i < Hh * Nn; i += 256) {
        int hh = i / Nn, l = i - hh * Nn;
        a_s[hh][l] = attn[(((size_t)b * Hh + hh) * Nn + n) * Nn + l];
    }
    __syncthreads();
    for (int i = tid; i < Hh * Nn; i += 256) {
        int kk = i / Nn, l = i - kk * Nn;
        float s = 0.f;
        #pragma unroll
        for (int hh = 0; hh < Hh; hh++) s = fmaf(a_s[hh][l], c_s[hh][kk], s);
        m_s[kk][l] = s;
    }
    __syncthreads();
    for (int j = tid; j < Dd; j += 256) {
        int kk = j >> 6, d = j & 63;
        const float* vp = v + (((size_t)b * Hh + kk) * Nn) * HD + d;
        const float* mr = m_s[kk];
        float s = 0.f;
        #pragma unroll 4
        for (int l = 0; l < Nn; l++) s = fmaf(mr[l], vp[(size_t)l * HD], s);
        y[(size_t)bn * Dd + j] = to_tf32(s);
    }
}

// ---------------- launcher ----------------
extern "C" void kernel_launch(void* const* d_in, const int* in_sizes, int n_in,
                              void* d_out, int out_size)
{
    const float* x             = (const float*)d_in[0];
    const float* w_qkv         = (const float*)d_in[1];
    const float* q_bias        = (const float*)d_in[2];
    const float* v_bias        = (const float*)d_in[3];
    const float* ssf_scale_qkv = (const float*)d_in[4];
    const float* ssf_shift_qkv = (const float*)d_in[5];
    const float* rel_table     = (const float*)d_in[6];
    const float* bases_coeff   = (const float*)d_in[7];
    const float* w_proj        = (const float*)d_in[8];
    const float* b_proj        = (const float*)d_in[9];
    const float* ssf_scale_pr  = (const float*)d_in[10];
    const float* ssf_shift_pr  = (const float*)d_in[11];
    const float* norm1_w       = (const float*)d_in[12];
    const float* norm1_b       = (const float*)d_in[13];
    const float* norm2_w       = (const float*)d_in[14];
    const float* norm2_b       = (const float*)d_in[15];
    const float* ssf_scale_1   = (const float*)d_in[16];
    const float* ssf_shift_1   = (const float*)d_in[17];
    const float* ssf_scale_2   = (const float*)d_in[18];
    const float* ssf_shift_2   = (const float*)d_in[19];
    const float* w_fc1         = (const float*)d_in[20];
    const float* b_fc1         = (const float*)d_in[21];
    const float* w_fc2         = (const float*)d_in[22];
    const float* b_fc2         = (const float*)d_in[23];
    const float* ssf_scale_mlp = (const float*)d_in[24];
    const float* ssf_shift_mlp = (const float*)d_in[25];
    const float* gamma_1       = (const float*)d_in[26];
    const float* gamma_2       = (const float*)d_in[27];
    const int*   rel_pos_index = (const int*)d_in[28];
    float* out = (float*)d_out;

    float *ph, *pq, *pk, *pv, *pattn, *py, *px1, *pm, *pwq, *pwp, *pw1, *pw2;
    cudaGetSymbolAddress((void**)&ph,    g_h);
    cudaGetSymbolAddress((void**)&pq,    g_q);
    cudaGetSymbolAddress((void**)&pk,    g_k);
    cudaGetSymbolAddress((void**)&pv,    g_v);
    cudaGetSymbolAddress((void**)&pattn, g_attn);
    cudaGetSymbolAddress((void**)&py,    g_y);
    cudaGetSymbolAddress((void**)&px1,   g_x1);
    cudaGetSymbolAddress((void**)&pm,    g_m);
    cudaGetSymbolAddress((void**)&pwq,   g_wq);
    cudaGetSymbolAddress((void**)&pwp,   g_wp);
    cudaGetSymbolAddress((void**)&pw1,   g_w1);
    cudaGetSymbolAddress((void**)&pw2,   g_w2);

    cudaFuncSetAttribute(gemm_mma<0>, cudaFuncAttributeMaxDynamicSharedMemorySize, GEMM_SMEM);
    cudaFuncSetAttribute(gemm_mma<1>, cudaFuncAttributeMaxDynamicSharedMemorySize, GEMM_SMEM);
    cudaFuncSetAttribute(gemm_mma<2>, cudaFuncAttributeMaxDynamicSharedMemorySize, GEMM_SMEM);
    cudaFuncSetAttribute(gemm_mma<3>, cudaFuncAttributeMaxDynamicSharedMemorySize, GEMM_SMEM);

    const int MT = (ROWS + 127) / 128;   // 99

    // 0. round weights to tf32 (rna — kills truncation bias)
    rna_kernel<<<(3*Dd*Dd/4 + 255)/256, 256>>>(w_qkv, pwq, 3*Dd*Dd/4);
    rna_kernel<<<(Dd*Dd/4   + 255)/256, 256>>>(w_proj, pwp, Dd*Dd/4);
    rna_kernel<<<(MLPD*Dd/4 + 255)/256, 256>>>(w_fc1, pw1, MLPD*Dd/4);
    rna_kernel<<<(Dd*MLPD/4 + 255)/256, 256>>>(w_fc2, pw2, Dd*MLPD/4);

    // 1. LN1 + SSF
    ln_ssf_kernel<<<ROWS, 256>>>(x, norm1_w, norm1_b, ssf_scale_1, ssf_shift_1, ph);

    // 2. QKV GEMM + bias + SSF + scatter
    {
        EpiP p = {};
        p.scale = ssf_scale_qkv; p.shift = ssf_shift_qkv;
        p.out = pq; p.outk = pk; p.outv = pv;
        p.qb = q_bias; p.vb = v_bias;
        gemm_mma<0><<<dim3(3*Dd/128, MT), 256, GEMM_SMEM>>>(ph, pwq, ROWS, 3*Dd, Dd, p);
    }

    // 3. attention scores + rel bias + softmax
    {
        int smem = (197 * 65 + 8 * 64) * sizeof(float);
        cudaFuncSetAttribute(attn_scores_kernel,
                             cudaFuncAttributeMaxDynamicSharedMemorySize, smem);
        attn_scores_kernel<<<Bb * Hh, 256, smem>>>(pq, pk, rel_table, rel_pos_index, pattn);
    }

    // 4. DCF head mix + attn@V
    mix_av_kernel<<<ROWS, 256>>>(pattn, pv, bases_coeff, py);

    // 5. proj GEMM + SSF + gamma1 residual
    {
        EpiP p = {};
        p.bias = b_proj; p.scale = ssf_scale_pr; p.shift = ssf_shift_pr;
        p.resid = x; p.gamma = gamma_1; p.out = px1;
        gemm_mma<1><<<dim3(Dd/128, MT), 256, GEMM_SMEM>>>(py, pwp, ROWS, Dd, Dd, p);
    }

    // 6. LN2 + SSF
    ln_ssf_kernel<<<ROWS, 256>>>(px1, norm2_w, norm2_b, ssf_scale_2, ssf_shift_2, ph);

    // 7. fc1 GEMM + GELU
    {
        EpiP p = {};
        p.bias = b_fc1; p.out = pm;
        gemm_mma<2><<<dim3(MLPD/128, MT), 256, GEMM_SMEM>>>(ph, pw1, ROWS, MLPD, Dd, p);
    }

    // 8. fc2 GEMM + SSF + gamma2 residual -> out
    {
        EpiP p = {};
        p.bias = b_fc2; p.scale = ssf_scale_mlp; p.shift = ssf_shift_mlp;
        p.resid = px1; p.gamma = gamma_2; p.out = out;
        gemm_mma<3><<<dim3(Dd/128, MT), 256, GEMM_SMEM>>>(pm, pw2, ROWS, Dd, MLPD, p);
    }
}

// round 6
// speedup vs baseline: 1.9675x; 1.2137x over previous
#include <cuda_runtime.h>
#include <math.h>
#include <stdint.h>

// ---------------- problem constants ----------------
#define Bb   64
#define Nn   197
#define Dd   768
#define Hh   12
#define HD   64
#define MLPD 3072
#define ROWS (Bb*Nn)          // 12608
#define LP   224              // padded l-stride (7*32, 16B aligned)

// ---------------- scratch (static device globals; no allocation) ----------------
__device__ float g_h [ (size_t)ROWS * Dd ];
__device__ float g_q [ (size_t)Bb * Hh * Nn * HD ];
__device__ float g_k [ (size_t)Bb * Hh * Nn * HD ];
__device__ float g_vt[ (size_t)Bb * Hh * HD * LP ];     // V^T [b,h,d,l] padded
__device__ float g_attn[ (size_t)Bb * Hh * Nn * LP ];   // [b,h,n,l] padded (pads stay 0)
__device__ float g_mix [ (size_t)Bb * Hh * Nn * LP ];   // mixed attn, padded
__device__ float g_y [ (size_t)ROWS * Dd ];
__device__ float g_x1[ (size_t)ROWS * Dd ];
__device__ float g_m [ (size_t)ROWS * MLPD ];
// tf32-rounded weight copies
__device__ float g_wq[ (size_t)3 * Dd * Dd ];
__device__ float g_wp[ (size_t)Dd * Dd ];
__device__ float g_w1[ (size_t)MLPD * Dd ];
__device__ float g_w2[ (size_t)Dd * MLPD ];

// ---------------- PTX helpers ----------------
__device__ __forceinline__ uint32_t smem_u32(const void* p) {
    uint32_t a;
    asm("{ .reg .u64 t; cvta.to.shared.u64 t, %1; cvt.u32.u64 %0, t; }" : "=r"(a) : "l"(p));
    return a;
}
__device__ __forceinline__ float to_tf32(float x) {
    uint32_t o;
    asm("cvt.rna.tf32.f32 %0, %1;" : "=r"(o) : "f"(x));
    return __uint_as_float(o);
}
__device__ __forceinline__ void cp16(uint32_t dst, const void* src) {
    asm volatile("cp.async.cg.shared.global [%0], [%1], 16;" :: "r"(dst), "l"(src));
}
__device__ __forceinline__ void sts_zero16(uint32_t dst) {
    asm volatile("st.shared.v4.b32 [%0], {%1,%1,%1,%1};" :: "r"(dst), "r"(0u));
}
__device__ __forceinline__ void cp_commit() { asm volatile("cp.async.commit_group;" ::: "memory"); }
template<int N>
__device__ __forceinline__ void cp_wait() { asm volatile("cp.async.wait_group %0;" :: "n"(N) : "memory"); }

__device__ __forceinline__ void ldsm4(uint32_t& r0, uint32_t& r1, uint32_t& r2, uint32_t& r3,
                                      uint32_t addr) {
    asm volatile("ldmatrix.sync.aligned.m8n8.x4.shared.b16 {%0,%1,%2,%3}, [%4];"
        : "=r"(r0), "=r"(r1), "=r"(r2), "=r"(r3) : "r"(addr));
}

// tf32 warp MMA: D(16x8) += A(16x8) * B(8x8)   [row.col]
__device__ __forceinline__ void mma_tf32(float* c, const uint32_t* a, const uint32_t* b) {
    asm volatile(
        "mma.sync.aligned.m16n8k8.row.col.f32.tf32.tf32.f32 "
        "{%0,%1,%2,%3}, {%4,%5,%6,%7}, {%8,%9}, {%0,%1,%2,%3};"
        : "+f"(c[0]), "+f"(c[1]), "+f"(c[2]), "+f"(c[3])
        : "r"(a[0]), "r"(a[1]), "r"(a[2]), "r"(a[3]), "r"(b[0]), "r"(b[1]));
}

// ---------------- epilogue params ----------------
struct EpiP {
    const float* bias;
    const float* scale;
    const float* shift;
    const float* resid;
    const float* gamma;
    float* out;
    float* outk;
    float* outv;
    const float* qb;
    const float* vb;
};

// per-element epilogue
// EPI: 0=qkv scatter (v->VT), 1=proj(+resid,g1), 2=gelu, 3=fc2(+resid,g2), 4=AV out
template<int EPI>
__device__ __forceinline__ void epi_store(int r, int c, float a, int N_, const EpiP& p, int z) {
    if constexpr (EPI == 0) {
        int part = c / Dd;
        int rr = c - part * Dd;
        float bias = (part == 0) ? p.qb[rr] : (part == 2 ? p.vb[rr] : 0.f);
        float val = (a + bias) * p.scale[c] + p.shift[c];
        int b_ = r / Nn, n_ = r - b_ * Nn;
        int hh = rr >> 6, d = rr & 63;
        if (part == 0)
            p.out[((((size_t)b_ * Hh + hh) * Nn) + n_) * HD + d] = val * 0.125f;
        else if (part == 1)
            p.outk[((((size_t)b_ * Hh + hh) * Nn) + n_) * HD + d] = val;
        else
            p.outv[(((size_t)b_ * Hh + hh) * HD + d) * LP + n_] = to_tf32(val);
    } else if constexpr (EPI == 1 || EPI == 3) {
        float val = (a + p.bias[c]) * p.scale[c] + p.shift[c];
        size_t idx = (size_t)r * N_ + c;
        p.out[idx] = p.resid[idx] + p.gamma[c] * val;
    } else if constexpr (EPI == 2) { // GELU (tf32-rounded: feeds fc2 GEMM)
        float v = a + p.bias[c];
        size_t idx = (size_t)r * N_ + c;
        p.out[idx] = to_tf32(0.5f * v * (1.f + erff(v * 0.70710678118654752f)));
    } else { // EPI == 4: AV output -> y[b][n][k*64+d], tf32 (feeds proj)
        int bb = z / Hh, hk = z - bb * Hh;
        p.out[((size_t)bb * Nn + r) * Dd + hk * HD + c] = to_tf32(a);
    }
}

// ---------------- mma.sync tf32 GEMM:  C[M,N_] = A[M,K] * B[N_,K]^T ----------------
// 128xBN block tile, 8 warps, K-slab 32, 3-stage cp.async, ldmatrix fragments.
#define PSTRIDE 36                       // padded floats per smem row
#define SLABF   (2 * 128 * PSTRIDE)      // floats per stage (A+B regions)
#define GSTAGES 3
#define GEMM_SMEM (GSTAGES * SLABF * 4)  // 110592 B

template<int EPI, int BN>
__global__ __launch_bounds__(256, 1) void gemm_mma(
    const float* __restrict__ A, const float* __restrict__ Bw,
    int M, int N_, int K, EpiP p)
{
    constexpr int WCOLS = BN / 32;        // warps along N: 4 (BN=128) or 2 (BN=64)
    constexpr int MT = WCOLS;             // m16-tiles per warp along M: 128/(16*(8/WCOLS))
    extern __shared__ float sm[];
    int tid = threadIdx.x;
    int row0 = blockIdx.y << 7, col0 = blockIdx.x * BN;
    int z = blockIdx.z;
    if constexpr (EPI == 4) {
        A  += (size_t)z * (Nn * LP);
        Bw += (size_t)z * (HD * LP);
    }
    int warp = tid >> 5, lane = tid & 31;
    int wm = warp / WCOLS, wn = warp % WCOLS;
    int g = lane >> 2, t = lane & 3;
    int q = lane >> 3, ri = lane & 7;

    // ---- loaders: threads 0..127 -> A rows, 128..128+BN-1 -> B rows ----
    bool isB = tid >= 128;
    int lr = tid & 127;
    bool lactive = isB ? (lr < BN) : true;
    bool lvalid = isB ? true : (row0 + lr < M);
    const float* gsrc = isB ? (Bw + (size_t)(col0 + lr) * K)
                            : (A  + (size_t)(row0 + lr) * K);
    uint32_t smbase = smem_u32(sm);
    uint32_t sdst = smbase + (uint32_t)((isB ? 128 * PSTRIDE : 0) + lr * PSTRIDE) * 4u;

    auto load_slab = [&](int slab, int stage) {
        if (!lactive) return;
        uint32_t dst = sdst + (uint32_t)stage * (SLABF * 4u);
        const float* src = gsrc + slab * 32;
        if (lvalid) {
            #pragma unroll
            for (int j = 0; j < 8; j++) cp16(dst + j * 16, src + j * 4);
        } else {
            #pragma unroll
            for (int j = 0; j < 8; j++) sts_zero16(dst + j * 16);
        }
    };

    // ---- per-thread ldmatrix base addresses ----
    // A frag regs: r0=[g][t] r1=[g+8][t] r2=[g][t+4] r3=[g+8][t+4]
    uint32_t a_base = smbase
        + (uint32_t)(wm * (MT * 16) * PSTRIDE * 4)
        + (uint32_t)((((q & 1) * 8 + ri) * PSTRIDE + (q >> 1) * 4) * 4);
    // B frag regs: r0=b0(nt even) r1=b1(nt even) r2=b0(nt odd) r3=b1(nt odd)
    uint32_t b_base = smbase
        + (uint32_t)((128 + wn * 32) * PSTRIDE * 4)
        + (uint32_t)((((q >> 1) * 8 + ri) * PSTRIDE + (q & 1) * 4) * 4);

    float c[MT][4][4];
    #pragma unroll
    for (int i = 0; i < MT; i++)
        #pragma unroll
        for (int j = 0; j < 4; j++)
            { c[i][j][0] = 0.f; c[i][j][1] = 0.f; c[i][j][2] = 0.f; c[i][j][3] = 0.f; }

    const int nslab = K >> 5;
    load_slab(0, 0); cp_commit();
    if (nslab > 1) load_slab(1, 1);
    cp_commit();

    for (int s = 0; s < nslab; s++) {
        cp_wait<1>();
        __syncthreads();
        if (s + 2 < nslab) load_slab(s + 2, (s + 2) % GSTAGES);
        cp_commit();

        uint32_t stg = (uint32_t)(s % GSTAGES) * (SLABF * 4u);
        #pragma unroll
        for (int kk = 0; kk < 4; kk++) {
            uint32_t coff = stg + (uint32_t)kk * 32u;
            uint32_t af[MT][4];
            #pragma unroll
            for (int mt = 0; mt < MT; mt++)
                ldsm4(af[mt][0], af[mt][1], af[mt][2], af[mt][3],
                      a_base + coff + (uint32_t)(mt * 16 * PSTRIDE * 4));
            uint32_t bf[4][2];
            #pragma unroll
            for (int ntp = 0; ntp < 2; ntp++)
                ldsm4(bf[2*ntp][0], bf[2*ntp][1], bf[2*ntp+1][0], bf[2*ntp+1][1],
                      b_base + coff + (uint32_t)(ntp * 16 * PSTRIDE * 4));
            #pragma unroll
            for (int mt = 0; mt < MT; mt++)
                #pragma unroll
                for (int nt = 0; nt < 4; nt++)
                    mma_tf32(c[mt][nt], af[mt], bf[nt]);
        }
    }
    cp_wait<0>();

    // ---- epilogue ----
    #pragma unroll
    for (int mt = 0; mt < MT; mt++) {
        int r_lo = row0 + wm * (MT * 16) + mt * 16 + g;
        int r_hi = r_lo + 8;
        #pragma unroll
        for (int nt = 0; nt < 4; nt++) {
            int cc = col0 + wn * 32 + nt * 8 + t * 2;
            if (r_lo < M) {
                epi_store<EPI>(r_lo, cc,     c[mt][nt][0], N_, p, z);
                epi_store<EPI>(r_lo, cc + 1, c[mt][nt][1], N_, p, z);
            }
            if (r_hi < M) {
                epi_store<EPI>(r_hi, cc,     c[mt][nt][2], N_, p, z);
                epi_store<EPI>(r_hi, cc + 1, c[mt][nt][3], N_, p, z);
            }
        }
    }
}

// ---------------- rna weight conversion ----------------
__global__ __launch_bounds__(256) void rna_kernel(const float* __restrict__ in,
                                                  float* __restrict__ out, int n4)
{
    int i = blockIdx.x * 256 + threadIdx.x;
    if (i < n4) {
        float4 v = ((const float4*)in)[i];
        v.x = to_tf32(v.x); v.y = to_tf32(v.y); v.z = to_tf32(v.z); v.w = to_tf32(v.w);
        ((float4*)out)[i] = v;
    }
}

// ---------------- LayerNorm + SSF (output tf32: feeds GEMM) ----------------
__global__ __launch_bounds__(256) void ln_ssf_kernel(
    const float* __restrict__ x, const float* __restrict__ w, const float* __restrict__ b,
    const float* __restrict__ sc, const float* __restrict__ sh, float* __restrict__ out)
{
    int row = blockIdx.x;
    const float* xr = x + (size_t)row * Dd;
    float* orow = out + (size_t)row * Dd;
    int tid = threadIdx.x;
    float v0 = xr[tid], v1 = xr[tid + 256], v2 = xr[tid + 512];
    float s = v0 + v1 + v2;
    __shared__ float red[8];
    int lane = tid & 31, wp = tid >> 5;
    #pragma unroll
    for (int o = 16; o; o >>= 1) s += __shfl_xor_sync(~0u, s, o);
    if (!lane) red[wp] = s;
    __syncthreads();
    float tot = red[0]+red[1]+red[2]+red[3]+red[4]+red[5]+red[6]+red[7];
    float mean = tot * (1.f / 768.f);
    float d0 = v0 - mean, d1 = v1 - mean, d2 = v2 - mean;
    float vs = d0*d0 + d1*d1 + d2*d2;
    #pragma unroll
    for (int o = 16; o; o >>= 1) vs += __shfl_xor_sync(~0u, vs, o);
    __syncthreads();
    if (!lane) red[wp] = vs;
    __syncthreads();
    float var = (red[0]+red[1]+red[2]+red[3]+red[4]+red[5]+red[6]+red[7]) * (1.f / 768.f);
    float inv = rsqrtf(var + 1e-5f);
    orow[tid]       = to_tf32((d0*inv*w[tid]       + b[tid])       * sc[tid]       + sh[tid]);
    orow[tid + 256] = to_tf32((d1*inv*w[tid + 256] + b[tid + 256]) * sc[tid + 256] + sh[tid + 256]);
    orow[tid + 512] = to_tf32((d2*inv*w[tid + 512] + b[tid + 512]) * sc[tid + 512] + sh[tid + 512]);
}

// ---------------- attention scores + softmax (block per (b,h)); padded out ----------------
__global__ __launch_bounds__(256) void attn_scores_kernel(
    const float* __restrict__ q, const float* __restrict__ k,
    const float* __restrict__ table, const int* __restrict__ relidx,
    float* __restrict__ attn)
{
    extern __shared__ float smem[];
    float* ks = smem;                 // 197*65
    float* qrow = smem + 197 * 65;    // 8*64
    int bh = blockIdx.x;
    int h = bh % Hh;
    const float* kbase = k + (size_t)bh * Nn * HD;
    for (int i = threadIdx.x; i < Nn * HD; i += blockDim.x)
        ks[(i >> 6) * 65 + (i & 63)] = kbase[i];
    __syncthreads();

    int w = threadIdx.x >> 5, lane = threadIdx.x & 31;
    const float* qbase = q + (size_t)bh * Nn * HD;
    float* abase = attn + (size_t)bh * Nn * LP;
    float* qs = qrow + w * 64;

    for (int n = w; n < Nn; n += 8) {
        qs[lane]      = qbase[n * 64 + lane];
        qs[lane + 32] = qbase[n * 64 + lane + 32];
        __syncwarp();
        float sc[7];
        int cnt = 0;
        float mx = -1e30f;
        for (int m = lane; m < Nn; m += 32) {
            float s = 0.f;
            const float* kr = &ks[m * 65];
            #pragma unroll
            for (int d = 0; d < 64; d++) s = fmaf(qs[d], kr[d], s);
            s += table[relidx[n * Nn + m] * Hh + h];
            sc[cnt++] = s;
            mx = fmaxf(mx, s);
        }
        #pragma unroll
        for (int o = 16; o; o >>= 1) mx = fmaxf(mx, __shfl_xor_sync(~0u, mx, o));
        float sum = 0.f;
        for (int i = 0; i < cnt; i++) { sc[i] = __expf(sc[i] - mx); sum += sc[i]; }
        #pragma unroll
        for (int o = 16; o; o >>= 1) sum += __shfl_xor_sync(~0u, sum, o);
        float inv = 1.f / sum;
        cnt = 0;
        for (int m = lane; m < Nn; m += 32) abase[n * LP + m] = sc[cnt++] * inv;
        __syncwarp();
    }
}

// ---------------- DCF head mix: P[b,k,n,:] = sum_h c[h,k] * attn[b,h,n,:] ----------------
__global__ __launch_bounds__(256) void mix_kernel(
    const float* __restrict__ attn, const float* __restrict__ bases,
    float* __restrict__ outp)
{
    __shared__ float4 a_s[Hh][LP/4];
    __shared__ float c_s[Hh][Hh];
    int bn = blockIdx.x;
    int b = bn / Nn, n = bn - b * Nn;
    int tid = threadIdx.x;
    if (tid < 144) {
        int kk = tid / 12, hh = tid % 12;
        c_s[hh][kk] = bases[kk * Hh + hh] + (hh == kk ? 1.f : 0.f);
    }
    const float4* af = (const float4*)attn;
    float4* of = (float4*)outp;
    const int L4 = LP / 4;  // 56
    for (int i = tid; i < Hh * L4; i += 256) {
        int hh = i / L4, l4 = i - hh * L4;
        a_s[hh][l4] = af[(((size_t)b * Hh + hh) * Nn + n) * L4 + l4];
    }
    __syncthreads();
    for (int i = tid; i < Hh * L4; i += 256) {
        int kk = i / L4, l4 = i - kk * L4;
        float4 acc = make_float4(0.f, 0.f, 0.f, 0.f);
        #pragma unroll
        for (int hh = 0; hh < Hh; hh++) {
            float cv = c_s[hh][kk];
            float4 av = a_s[hh][l4];
            acc.x = fmaf(cv, av.x, acc.x);
            acc.y = fmaf(cv, av.y, acc.y);
            acc.z = fmaf(cv, av.z, acc.z);
            acc.w = fmaf(cv, av.w, acc.w);
        }
        acc.x = to_tf32(acc.x); acc.y = to_tf32(acc.y);
        acc.z = to_tf32(acc.z); acc.w = to_tf32(acc.w);
        of[(((size_t)b * Hh + kk) * Nn + n) * L4 + l4] = acc;
    }
}

// ---------------- launcher ----------------
extern "C" void kernel_launch(void* const* d_in, const int* in_sizes, int n_in,
                              void* d_out, int out_size)
{
    const float* x             = (const float*)d_in[0];
    const float* w_qkv         = (const float*)d_in[1];
    const float* q_bias        = (const float*)d_in[2];
    const float* v_bias        = (const float*)d_in[3];
    const float* ssf_scale_qkv = (const float*)d_in[4];
    const float* ssf_shift_qkv = (const float*)d_in[5];
    const float* rel_table     = (const float*)d_in[6];
    const float* bases_coeff   = (const float*)d_in[7];
    const float* w_proj        = (const float*)d_in[8];
    const float* b_proj        = (const float*)d_in[9];
    const float* ssf_scale_pr  = (const float*)d_in[10];
    const float* ssf_shift_pr  = (const float*)d_in[11];
    const float* norm1_w       = (const float*)d_in[12];
    const float* norm1_b       = (const float*)d_in[13];
    const float* norm2_w       = (const float*)d_in[14];
    const float* norm2_b       = (const float*)d_in[15];
    const float* ssf_scale_1   = (const float*)d_in[16];
    const float* ssf_shift_1   = (const float*)d_in[17];
    const float* ssf_scale_2   = (const float*)d_in[18];
    const float* ssf_shift_2   = (const float*)d_in[19];
    const float* w_fc1         = (const float*)d_in[20];
    const float* b_fc1         = (const float*)d_in[21];
    const float* w_fc2         = (const float*)d_in[22];
    const float* b_fc2         = (const float*)d_in[23];
    const float* ssf_scale_mlp = (const float*)d_in[24];
    const float* ssf_shift_mlp = (const float*)d_in[25];
    const float* gamma_1       = (const float*)d_in[26];
    const float* gamma_2       = (const float*)d_in[27];
    const int*   rel_pos_index = (const int*)d_in[28];
    float* out = (float*)d_out;

    float *ph, *pq, *pk, *pvt, *pattn, *pmix, *py, *px1, *pm, *pwq, *pwp, *pw1, *pw2;
    cudaGetSymbolAddress((void**)&ph,    g_h);
    cudaGetSymbolAddress((void**)&pq,    g_q);
    cudaGetSymbolAddress((void**)&pk,    g_k);
    cudaGetSymbolAddress((void**)&pvt,   g_vt);
    cudaGetSymbolAddress((void**)&pattn, g_attn);
    cudaGetSymbolAddress((void**)&pmix,  g_mix);
    cudaGetSymbolAddress((void**)&py,    g_y);
    cudaGetSymbolAddress((void**)&px1,   g_x1);
    cudaGetSymbolAddress((void**)&pm,    g_m);
    cudaGetSymbolAddress((void**)&pwq,   g_wq);
    cudaGetSymbolAddress((void**)&pwp,   g_wp);
    cudaGetSymbolAddress((void**)&pw1,   g_w1);
    cudaGetSymbolAddress((void**)&pw2,   g_w2);

    cudaFuncSetAttribute(gemm_mma<0,128>, cudaFuncAttributeMaxDynamicSharedMemorySize, GEMM_SMEM);
    cudaFuncSetAttribute(gemm_mma<1,128>, cudaFuncAttributeMaxDynamicSharedMemorySize, GEMM_SMEM);
    cudaFuncSetAttribute(gemm_mma<2,128>, cudaFuncAttributeMaxDynamicSharedMemorySize, GEMM_SMEM);
    cudaFuncSetAttribute(gemm_mma<3,128>, cudaFuncAttributeMaxDynamicSharedMemorySize, GEMM_SMEM);
    cudaFuncSetAttribute(gemm_mma<4,64>,  cudaFuncAttributeMaxDynamicSharedMemorySize, GEMM_SMEM);

    const int MT_ = (ROWS + 127) / 128;   // 99

    // 0. round weights to tf32 (rna)
    rna_kernel<<<(3*Dd*Dd/4 + 255)/256, 256>>>(w_qkv, pwq, 3*Dd*Dd/4);
    rna_kernel<<<(Dd*Dd/4   + 255)/256, 256>>>(w_proj, pwp, Dd*Dd/4);
    rna_kernel<<<(MLPD*Dd/4 + 255)/256, 256>>>(w_fc1, pw1, MLPD*Dd/4);
    rna_kernel<<<(Dd*MLPD/4 + 255)/256, 256>>>(w_fc2, pw2, Dd*MLPD/4);

    // 1. LN1 + SSF
    ln_ssf_kernel<<<ROWS, 256>>>(x, norm1_w, norm1_b, ssf_scale_1, ssf_shift_1, ph);

    // 2. QKV GEMM + bias + SSF + scatter (v -> V^T)
    {
        EpiP p = {};
        p.scale = ssf_scale_qkv; p.shift = ssf_shift_qkv;
        p.out = pq; p.outk = pk; p.outv = pvt;
        p.qb = q_bias; p.vb = v_bias;
        gemm_mma<0,128><<<dim3(3*Dd/128, MT_), 256, GEMM_SMEM>>>(ph, pwq, ROWS, 3*Dd, Dd, p);
    }

    // 3. attention scores + rel bias + softmax (padded l-stride)
    {
        int smem = (197 * 65 + 8 * 64) * sizeof(float);
        cudaFuncSetAttribute(attn_scores_kernel,
                             cudaFuncAttributeMaxDynamicSharedMemorySize, smem);
        attn_scores_kernel<<<Bb * Hh, 256, smem>>>(pq, pk, rel_table, rel_pos_index, pattn);
    }

    // 4a. DCF head mix
    mix_kernel<<<ROWS, 256>>>(pattn, bases_coeff, pmix);

    // 4b. AV batched GEMM: O[b,k][n,d] = P[b,k] @ V^T[b,k]^T
    {
        EpiP p = {};
        p.out = py;
        gemm_mma<4,64><<<dim3(1, 2, Bb*Hh), 256, GEMM_SMEM>>>(pmix, pvt, Nn, HD, LP, p);
    }

    // 5. proj GEMM + SSF + gamma1 residual
    {
        EpiP p = {};
        p.bias = b_proj; p.scale = ssf_scale_pr; p.shift = ssf_shift_pr;
        p.resid = x; p.gamma = gamma_1; p.out = px1;
        gemm_mma<1,128><<<dim3(Dd/128, MT_), 256, GEMM_SMEM>>>(py, pwp, ROWS, Dd, Dd, p);
    }

    // 6. LN2 + SSF
    ln_ssf_kernel<<<ROWS, 256>>>(px1, norm2_w, norm2_b, ssf_scale_2, ssf_shift_2, ph);

    // 7. fc1 GEMM + GELU
    {
        EpiP p = {};
        p.bias = b_fc1; p.out = pm;
        gemm_mma<2,128><<<dim3(MLPD/128, MT_), 256, GEMM_SMEM>>>(ph, pw1, ROWS, MLPD, Dd, p);
    }

    // 8. fc2 GEMM + SSF + gamma2 residual -> out
    {
        EpiP p = {};
        p.bias = b_fc2; p.scale = ssf_scale_mlp; p.shift = ssf_shift_mlp;
        p.resid = px1; p.gamma = gamma_2; p.out = out;
        gemm_mma<3,128><<<dim3(Dd/128, MT_), 256, GEMM_SMEM>>>(pm, pw2, ROWS, Dd, MLPD, p);
    }
}

// round 7
// speedup vs baseline: 3.4310x; 1.7438x over previous
#include <cuda_runtime.h>
#include <cuda_bf16.h>
#include <math.h>
#include <stdint.h>

// ---------------- problem constants ----------------
#define Bb   64
#define Nn   197
#define Dd   768
#define Hh   12
#define HD   64
#define MLPD 3072
#define ROWS (Bb*Nn)          // 12608
#define LP   224              // padded l-stride

typedef __nv_bfloat16 bf16;
typedef __nv_bfloat162 bf162;

// ---------------- scratch (static device globals; no allocation) ----------------
__device__ bf16  g_h [ (size_t)ROWS * Dd ];              // LN out (bf16, GEMM A)
__device__ float g_q [ (size_t)Bb * Hh * Nn * HD ];      // fp32 (softmax accuracy)
__device__ float g_k [ (size_t)Bb * Hh * Nn * HD ];
__device__ bf16  g_vt[ (size_t)Bb * Hh * HD * LP ];      // V^T [b,h,d,l] (pads stay 0)
__device__ float g_attn[ (size_t)Bb * Hh * Nn * LP ];    // softmax out (pads stay 0)
__device__ bf16  g_mix [ (size_t)Bb * Hh * Nn * LP ];    // mixed attn (bf16)
__device__ bf16  g_y [ (size_t)ROWS * Dd ];              // AV out (bf16, GEMM A)
__device__ float g_x1[ (size_t)ROWS * Dd ];              // residual 1 (fp32)
__device__ bf16  g_m [ (size_t)ROWS * MLPD ];            // GELU out (bf16, GEMM A)
// bf16 weight copies
__device__ bf16 g_wq[ (size_t)3 * Dd * Dd ];
__device__ bf16 g_wp[ (size_t)Dd * Dd ];
__device__ bf16 g_w1[ (size_t)MLPD * Dd ];
__device__ bf16 g_w2[ (size_t)Dd * MLPD ];

// ---------------- PTX helpers ----------------
__device__ __forceinline__ uint32_t smem_u32(const void* p) {
    uint32_t a;
    asm("{ .reg .u64 t; cvta.to.shared.u64 t, %1; cvt.u32.u64 %0, t; }" : "=r"(a) : "l"(p));
    return a;
}
__device__ __forceinline__ void cp16(uint32_t dst, const void* src) {
    asm volatile("cp.async.cg.shared.global [%0], [%1], 16;" :: "r"(dst), "l"(src));
}
__device__ __forceinline__ void sts_zero16(uint32_t dst) {
    asm volatile("st.shared.v4.b32 [%0], {%1,%1,%1,%1};" :: "r"(dst), "r"(0u));
}
__device__ __forceinline__ void cp_commit() { asm volatile("cp.async.commit_group;" ::: "memory"); }
template<int N>
__device__ __forceinline__ void cp_wait() { asm volatile("cp.async.wait_group %0;" :: "n"(N) : "memory"); }

__device__ __forceinline__ void ldsm4(uint32_t& r0, uint32_t& r1, uint32_t& r2, uint32_t& r3,
                                      uint32_t addr) {
    asm volatile("ldmatrix.sync.aligned.m8n8.x4.shared.b16 {%0,%1,%2,%3}, [%4];"
        : "=r"(r0), "=r"(r1), "=r"(r2), "=r"(r3) : "r"(addr));
}

// bf16 warp MMA: D(16x8) += A(16x16) * B(16x8)   [row.col]
__device__ __forceinline__ void mma_bf16(float* c, const uint32_t* a, const uint32_t* b) {
    asm volatile(
        "mma.sync.aligned.m16n8k16.row.col.f32.bf16.bf16.f32 "
        "{%0,%1,%2,%3}, {%4,%5,%6,%7}, {%8,%9}, {%0,%1,%2,%3};"
        : "+f"(c[0]), "+f"(c[1]), "+f"(c[2]), "+f"(c[3])
        : "r"(a[0]), "r"(a[1]), "r"(a[2]), "r"(a[3]), "r"(b[0]), "r"(b[1]));
}

// ---------------- epilogue params ----------------
struct EpiP {
    const float* bias;
    const float* scale;
    const float* shift;
    const float* resid;
    const float* gamma;
    float* out;      // fp32 outs: q (EPI0), x1 (EPI1), final (EPI3)
    float* outk;     // k fp32 (EPI0)
    bf16*  outb;     // bf16 outs: v->VT (EPI0), gelu (EPI2), AV y (EPI4)
    const float* qb;
    const float* vb;
};

// per-element epilogue
// EPI: 0=qkv scatter, 1=proj(+resid,g1), 2=gelu, 3=fc2(+resid,g2), 4=AV out
template<int EPI>
__device__ __forceinline__ void epi_store(int r, int c, float a, int N_, const EpiP& p, int z) {
    if constexpr (EPI == 0) {
        int part = c / Dd;
        int rr = c - part * Dd;
        float bias = (part == 0) ? p.qb[rr] : (part == 2 ? p.vb[rr] : 0.f);
        float val = (a + bias) * p.scale[c] + p.shift[c];
        int b_ = r / Nn, n_ = r - b_ * Nn;
        int hh = rr >> 6, d = rr & 63;
        if (part == 0)
            p.out[((((size_t)b_ * Hh + hh) * Nn) + n_) * HD + d] = val * 0.125f;
        else if (part == 1)
            p.outk[((((size_t)b_ * Hh + hh) * Nn) + n_) * HD + d] = val;
        else
            p.outb[(((size_t)b_ * Hh + hh) * HD + d) * LP + n_] = __float2bfloat16_rn(val);
    } else if constexpr (EPI == 1 || EPI == 3) {
        float val = (a + p.bias[c]) * p.scale[c] + p.shift[c];
        size_t idx = (size_t)r * N_ + c;
        p.out[idx] = p.resid[idx] + p.gamma[c] * val;
    } else if constexpr (EPI == 2) { // GELU -> bf16 (feeds fc2)
        float v = a + p.bias[c];
        size_t idx = (size_t)r * N_ + c;
        p.outb[idx] = __float2bfloat16_rn(0.5f * v * (1.f + erff(v * 0.70710678118654752f)));
    } else { // EPI == 4: AV out -> y[b][n][k*64+d] bf16 (feeds proj)
        int bb = z / Hh, hk = z - bb * Hh;
        p.outb[((size_t)bb * Nn + r) * Dd + hk * HD + c] = __float2bfloat16_rn(a);
    }
}

// ---------------- mma.sync bf16 GEMM:  C[M,N_] = A[M,K] * B[N_,K]^T ----------------
// 128xBN block tile, 8 warps, K-slab 32, 3-stage cp.async, ldmatrix fragments.
#define PSH    40                        // padded halves per smem row (80 B)
#define ROWB   80
#define AREGB  (128 * ROWB)              // 10240 B
#define STAGEB (2 * AREGB)               // 20480 B (A+B)
#define GSTAGES 3
#define GEMM_SMEM (GSTAGES * STAGEB)     // 61440 B

template<int EPI, int BN>
__global__ __launch_bounds__(256, 2) void gemm_mma(
    const bf16* __restrict__ A, const bf16* __restrict__ Bw,
    int M, int N_, int K, EpiP p)
{
    constexpr int WCOLS = BN / 32;        // warps along N
    constexpr int MT = WCOLS;             // m16-tiles per warp along M
    extern __shared__ char smc[];
    int tid = threadIdx.x;
    int row0 = blockIdx.y << 7, col0 = blockIdx.x * BN;
    int z = blockIdx.z;
    if constexpr (EPI == 4) {
        A  += (size_t)z * (Nn * LP);
        Bw += (size_t)z * (HD * LP);
    }
    int warp = tid >> 5, lane = tid & 31;
    int wm = warp / WCOLS, wn = warp % WCOLS;
    int g = lane >> 2, t = lane & 3;
    int q = lane >> 3, ri = lane & 7;

    // ---- loaders: threads 0..127 -> A rows, 128..128+BN-1 -> B rows ----
    bool isB = tid >= 128;
    int lr = tid & 127;
    bool lactive = isB ? (lr < BN) : true;
    bool lvalid = isB ? true : (row0 + lr < M);
    const bf16* gsrc = isB ? (Bw + (size_t)(col0 + lr) * K)
                           : (A  + (size_t)(row0 + lr) * K);
    uint32_t smbase = smem_u32(smc);
    uint32_t sdst = smbase + (uint32_t)((isB ? AREGB : 0) + lr * ROWB);

    auto load_slab = [&](int slab, int stage) {
        if (!lactive) return;
        uint32_t dst = sdst + (uint32_t)stage * STAGEB;
        const bf16* src = gsrc + slab * 32;
        if (lvalid) {
            #pragma unroll
            for (int j = 0; j < 4; j++) cp16(dst + j * 16, src + j * 8);
        } else {
            #pragma unroll
            for (int j = 0; j < 4; j++) sts_zero16(dst + j * 16);
        }
    };

    // ---- per-thread ldmatrix base addresses (bytes) ----
    // A x4: M0=rows0-7/k0-7, M1=rows8-15/k0-7, M2=rows0-7/k8-15, M3=rows8-15/k8-15
    uint32_t a_base = smbase
        + (uint32_t)(wm * (MT * 16) * ROWB)
        + (uint32_t)(((q & 1) * 8 + ri) * ROWB + (q >> 1) * 16);
    // B x4: M0=n0-7/k0, M1=n0-7/k8, M2=n8-15/k0, M3=n8-15/k8
    uint32_t b_base = smbase + AREGB
        + (uint32_t)(wn * 32 * ROWB)
        + (uint32_t)(((q >> 1) * 8 + ri) * ROWB + (q & 1) * 16);

    float c[MT][4][4];
    #pragma unroll
    for (int i = 0; i < MT; i++)
        #pragma unroll
        for (int j = 0; j < 4; j++)
            { c[i][j][0] = 0.f; c[i][j][1] = 0.f; c[i][j][2] = 0.f; c[i][j][3] = 0.f; }

    const int nslab = K >> 5;
    load_slab(0, 0); cp_commit();
    if (nslab > 1) load_slab(1, 1);
    cp_commit();

    for (int s = 0; s < nslab; s++) {
        cp_wait<1>();
        __syncthreads();
        if (s + 2 < nslab) load_slab(s + 2, (s + 2) % GSTAGES);
        cp_commit();

        uint32_t stg = (uint32_t)(s % GSTAGES) * STAGEB;
        #pragma unroll
        for (int kk = 0; kk < 2; kk++) {          // 2 x K=16 per 32-slab
            uint32_t coff = stg + (uint32_t)kk * 32u;   // 16 halves
            uint32_t af[MT][4];
            #pragma unroll
            for (int mt = 0; mt < MT; mt++)
                ldsm4(af[mt][0], af[mt][1], af[mt][2], af[mt][3],
                      a_base + coff + (uint32_t)(mt * 16 * ROWB));
            uint32_t bf[4][2];
            #pragma unroll
            for (int ntp = 0; ntp < 2; ntp++)
                ldsm4(bf[2*ntp][0], bf[2*ntp][1], bf[2*ntp+1][0], bf[2*ntp+1][1],
                      b_base + coff + (uint32_t)(ntp * 16 * ROWB));
            #pragma unroll
            for (int mt = 0; mt < MT; mt++)
                #pragma unroll
                for (int nt = 0; nt < 4; nt++)
                    mma_bf16(c[mt][nt], af[mt], bf[nt]);
        }
    }
    cp_wait<0>();

    // ---- epilogue ----
    #pragma unroll
    for (int mt = 0; mt < MT; mt++) {
        int r_lo = row0 + wm * (MT * 16) + mt * 16 + g;
        int r_hi = r_lo + 8;
        #pragma unroll
        for (int nt = 0; nt < 4; nt++) {
            int cc = col0 + wn * 32 + nt * 8 + t * 2;
            if (r_lo < M) {
                epi_store<EPI>(r_lo, cc,     c[mt][nt][0], N_, p, z);
                epi_store<EPI>(r_lo, cc + 1, c[mt][nt][1], N_, p, z);
            }
            if (r_hi < M) {
                epi_store<EPI>(r_hi, cc,     c[mt][nt][2], N_, p, z);
                epi_store<EPI>(r_hi, cc + 1, c[mt][nt][3], N_, p, z);
            }
        }
    }
}

// ---------------- fp32 -> bf16 weight conversion ----------------
__global__ __launch_bounds__(256) void cvt_bf16_kernel(const float* __restrict__ in,
                                                       bf16* __restrict__ out, int n4)
{
    int i = blockIdx.x * 256 + threadIdx.x;
    if (i < n4) {
        float4 v = ((const float4*)in)[i];
        bf162 lo = __float22bfloat162_rn(make_float2(v.x, v.y));
        bf162 hi = __float22bfloat162_rn(make_float2(v.z, v.w));
        ((bf162*)out)[i * 2]     = lo;
        ((bf162*)out)[i * 2 + 1] = hi;
    }
}

// ---------------- LayerNorm + SSF -> bf16 (feeds GEMM) ----------------
__global__ __launch_bounds__(256) void ln_ssf_kernel(
    const float* __restrict__ x, const float* __restrict__ w, const float* __restrict__ b,
    const float* __restrict__ sc, const float* __restrict__ sh, bf16* __restrict__ out)
{
    int row = blockIdx.x;
    const float* xr = x + (size_t)row * Dd;
    bf16* orow = out + (size_t)row * Dd;
    int tid = threadIdx.x;
    float v0 = xr[tid], v1 = xr[tid + 256], v2 = xr[tid + 512];
    float s = v0 + v1 + v2;
    __shared__ float red[8];
    int lane = tid & 31, wp = tid >> 5;
    #pragma unroll
    for (int o = 16; o; o >>= 1) s += __shfl_xor_sync(~0u, s, o);
    if (!lane) red[wp] = s;
    __syncthreads();
    float tot = red[0]+red[1]+red[2]+red[3]+red[4]+red[5]+red[6]+red[7];
    float mean = tot * (1.f / 768.f);
    float d0 = v0 - mean, d1 = v1 - mean, d2 = v2 - mean;
    float vs = d0*d0 + d1*d1 + d2*d2;
    #pragma unroll
    for (int o = 16; o; o >>= 1) vs += __shfl_xor_sync(~0u, vs, o);
    __syncthreads();
    if (!lane) red[wp] = vs;
    __syncthreads();
    float var = (red[0]+red[1]+red[2]+red[3]+red[4]+red[5]+red[6]+red[7]) * (1.f / 768.f);
    float inv = rsqrtf(var + 1e-5f);
    orow[tid]       = __float2bfloat16_rn((d0*inv*w[tid]       + b[tid])       * sc[tid]       + sh[tid]);
    orow[tid + 256] = __float2bfloat16_rn((d1*inv*w[tid + 256] + b[tid + 256]) * sc[tid + 256] + sh[tid + 256]);
    orow[tid + 512] = __float2bfloat16_rn((d2*inv*w[tid + 512] + b[tid + 512]) * sc[tid + 512] + sh[tid + 512]);
}

// ---------------- attention scores + softmax (block per (b,h)); fp32 ----------------
__global__ __launch_bounds__(256) void attn_scores_kernel(
    const float* __restrict__ q, const float* __restrict__ k,
    const float* __restrict__ table, const int* __restrict__ relidx,
    float* __restrict__ attn)
{
    extern __shared__ float smem[];
    float* ks = smem;                 // 197*65
    float* qrow = smem + 197 * 65;    // 8*64
    int bh = blockIdx.x;
    int h = bh % Hh;
    const float* kbase = k + (size_t)bh * Nn * HD;
    for (int i = threadIdx.x; i < Nn * HD; i += blockDim.x)
        ks[(i >> 6) * 65 + (i & 63)] = kbase[i];
    __syncthreads();

    int w = threadIdx.x >> 5, lane = threadIdx.x & 31;
    const float* qbase = q + (size_t)bh * Nn * HD;
    float* abase = attn + (size_t)bh * Nn * LP;
    float* qs = qrow + w * 64;

    for (int n = w; n < Nn; n += 8) {
        qs[lane]      = qbase[n * 64 + lane];
        qs[lane + 32] = qbase[n * 64 + lane + 32];
        __syncwarp();
        float sc[7];
        int cnt = 0;
        float mx = -1e30f;
        for (int m = lane; m < Nn; m += 32) {
            float s = 0.f;
            const float* kr = &ks[m * 65];
            #pragma unroll
            for (int d = 0; d < 64; d++) s = fmaf(qs[d], kr[d], s);
            s += table[relidx[n * Nn + m] * Hh + h];
            sc[cnt++] = s;
            mx = fmaxf(mx, s);
        }
        #pragma unroll
        for (int o = 16; o; o >>= 1) mx = fmaxf(mx, __shfl_xor_sync(~0u, mx, o));
        float sum = 0.f;
        for (int i = 0; i < cnt; i++) { sc[i] = __expf(sc[i] - mx); sum += sc[i]; }
        #pragma unroll
        for (int o = 16; o; o >>= 1) sum += __shfl_xor_sync(~0u, sum, o);
        float inv = 1.f / sum;
        cnt = 0;
        for (int m = lane; m < Nn; m += 32) abase[n * LP + m] = sc[cnt++] * inv;
        __syncwarp();
    }
}

// ---------------- DCF head mix -> bf16: P[b,k,n,:] = sum_h c[h,k]*attn[b,h,n,:] ----------------
__global__ __launch_bounds__(256) void mix_kernel(
    const float* __restrict__ attn, const float* __restrict__ bases,
    bf16* __restrict__ outp)
{
    __shared__ float4 a_s[Hh][LP/4];
    __shared__ float c_s[Hh][Hh];
    int bn = blockIdx.x;
    int b = bn / Nn, n = bn - b * Nn;
    int tid = threadIdx.x;
    if (tid < 144) {
        int kk = tid / 12, hh = tid % 12;
        c_s[hh][kk] = bases[kk * Hh + hh] + (hh == kk ? 1.f : 0.f);
    }
    const float4* af = (const float4*)attn;
    bf162* of = (bf162*)outp;
    const int L4 = LP / 4;  // 56
    for (int i = tid; i < Hh * L4; i += 256) {
        int hh = i / L4, l4 = i - hh * L4;
        a_s[hh][l4] = af[(((size_t)b * Hh + hh) * Nn + n) * L4 + l4];
    }
    __syncthreads();
    for (int i = tid; i < Hh * L4; i += 256) {
        int kk = i / L4, l4 = i - kk * L4;
        float4 acc = make_float4(0.f, 0.f, 0.f, 0.f);
        #pragma unroll
        for (int hh = 0; hh < Hh; hh++) {
            float cv = c_s[hh][kk];
            float4 av = a_s[hh][l4];
            acc.x = fmaf(cv, av.x, acc.x);
            acc.y = fmaf(cv, av.y, acc.y);
            acc.z = fmaf(cv, av.z, acc.z);
            acc.w = fmaf(cv, av.w, acc.w);
        }
        size_t base2 = ((((size_t)b * Hh + kk) * Nn + n) * LP) >> 1;
        of[base2 + l4 * 2]     = __float22bfloat162_rn(make_float2(acc.x, acc.y));
        of[base2 + l4 * 2 + 1] = __float22bfloat162_rn(make_float2(acc.z, acc.w));
    }
}

// ---------------- launcher ----------------
extern "C" void kernel_launch(void* const* d_in, const int* in_sizes, int n_in,
                              void* d_out, int out_size)
{
    const float* x             = (const float*)d_in[0];
    const float* w_qkv         = (const float*)d_in[1];
    const float* q_bias        = (const float*)d_in[2];
    const float* v_bias        = (const float*)d_in[3];
    const float* ssf_scale_qkv = (const float*)d_in[4];
    const float* ssf_shift_qkv = (const float*)d_in[5];
    const float* rel_table     = (const float*)d_in[6];
    const float* bases_coeff   = (const float*)d_in[7];
    const float* w_proj        = (const float*)d_in[8];
    const float* b_proj        = (const float*)d_in[9];
    const float* ssf_scale_pr  = (const float*)d_in[10];
    const float* ssf_shift_pr  = (const float*)d_in[11];
    const float* norm1_w       = (const float*)d_in[12];
    const float* norm1_b       = (const float*)d_in[13];
    const float* norm2_w       = (const float*)d_in[14];
    const float* norm2_b       = (const float*)d_in[15];
    const float* ssf_scale_1   = (const float*)d_in[16];
    const float* ssf_shift_1   = (const float*)d_in[17];
    const float* ssf_scale_2   = (const float*)d_in[18];
    const float* ssf_shift_2   = (const float*)d_in[19];
    const float* w_fc1         = (const float*)d_in[20];
    const float* b_fc1         = (const float*)d_in[21];
    const float* w_fc2         = (const float*)d_in[22];
    const float* b_fc2         = (const float*)d_in[23];
    const float* ssf_scale_mlp = (const float*)d_in[24];
    const float* ssf_shift_mlp = (const float*)d_in[25];
    const float* gamma_1       = (const float*)d_in[26];
    const float* gamma_2       = (const float*)d_in[27];
    const int*   rel_pos_index = (const int*)d_in[28];
    float* out = (float*)d_out;

    bf16 *ph, *pvt, *pmix, *py, *pm, *pwq, *pwp, *pw1, *pw2;
    float *pq, *pk, *pattn, *px1;
    cudaGetSymbolAddress((void**)&ph,    g_h);
    cudaGetSymbolAddress((void**)&pq,    g_q);
    cudaGetSymbolAddress((void**)&pk,    g_k);
    cudaGetSymbolAddress((void**)&pvt,   g_vt);
    cudaGetSymbolAddress((void**)&pattn, g_attn);
    cudaGetSymbolAddress((void**)&pmix,  g_mix);
    cudaGetSymbolAddress((void**)&py,    g_y);
    cudaGetSymbolAddress((void**)&px1,   g_x1);
    cudaGetSymbolAddress((void**)&pm,    g_m);
    cudaGetSymbolAddress((void**)&pwq,   g_wq);
    cudaGetSymbolAddress((void**)&pwp,   g_wp);
    cudaGetSymbolAddress((void**)&pw1,   g_w1);
    cudaGetSymbolAddress((void**)&pw2,   g_w2);

    cudaFuncSetAttribute(gemm_mma<0,128>, cudaFuncAttributeMaxDynamicSharedMemorySize, GEMM_SMEM);
    cudaFuncSetAttribute(gemm_mma<1,128>, cudaFuncAttributeMaxDynamicSharedMemorySize, GEMM_SMEM);
    cudaFuncSetAttribute(gemm_mma<2,128>, cudaFuncAttributeMaxDynamicSharedMemorySize, GEMM_SMEM);
    cudaFuncSetAttribute(gemm_mma<3,128>, cudaFuncAttributeMaxDynamicSharedMemorySize, GEMM_SMEM);
    cudaFuncSetAttribute(gemm_mma<4,64>,  cudaFuncAttributeMaxDynamicSharedMemorySize, GEMM_SMEM);

    const int MT_ = (ROWS + 127) / 128;   // 99

    // 0. weights -> bf16
    cvt_bf16_kernel<<<(3*Dd*Dd/4 + 255)/256, 256>>>(w_qkv, pwq, 3*Dd*Dd/4);
    cvt_bf16_kernel<<<(Dd*Dd/4   + 255)/256, 256>>>(w_proj, pwp, Dd*Dd/4);
    cvt_bf16_kernel<<<(MLPD*Dd/4 + 255)/256, 256>>>(w_fc1, pw1, MLPD*Dd/4);
    cvt_bf16_kernel<<<(Dd*MLPD/4 + 255)/256, 256>>>(w_fc2, pw2, Dd*MLPD/4);

    // 1. LN1 + SSF -> bf16
    ln_ssf_kernel<<<ROWS, 256>>>(x, norm1_w, norm1_b, ssf_scale_1, ssf_shift_1, ph);

    // 2. QKV GEMM + bias + SSF + scatter (q,k fp32; v -> V^T bf16)
    {
        EpiP p = {};
        p.scale = ssf_scale_qkv; p.shift = ssf_shift_qkv;
        p.out = pq; p.outk = pk; p.outb = pvt;
        p.qb = q_bias; p.vb = v_bias;
        gemm_mma<0,128><<<dim3(3*Dd/128, MT_), 256, GEMM_SMEM>>>(ph, pwq, ROWS, 3*Dd, Dd, p);
    }

    // 3. attention scores + rel bias + softmax (fp32)
    {
        int smem = (197 * 65 + 8 * 64) * sizeof(float);
        cudaFuncSetAttribute(attn_scores_kernel,
                             cudaFuncAttributeMaxDynamicSharedMemorySize, smem);
        attn_scores_kernel<<<Bb * Hh, 256, smem>>>(pq, pk, rel_table, rel_pos_index, pattn);
    }

    // 4a. DCF head mix -> bf16
    mix_kernel<<<ROWS, 256>>>(pattn, bases_coeff, pmix);

    // 4b. AV batched GEMM: O[b,k][n,d] = P[b,k] @ V^T[b,k]^T
    {
        EpiP p = {};
        p.outb = py;
        gemm_mma<4,64><<<dim3(1, 2, Bb*Hh), 256, GEMM_SMEM>>>(pmix, pvt, Nn, HD, LP, p);
    }

    // 5. proj GEMM + SSF + gamma1 residual (fp32 out)
    {
        EpiP p = {};
        p.bias = b_proj; p.scale = ssf_scale_pr; p.shift = ssf_shift_pr;
        p.resid = x; p.gamma = gamma_1; p.out = px1;
        gemm_mma<1,128><<<dim3(Dd/128, MT_), 256, GEMM_SMEM>>>(py, pwp, ROWS, Dd, Dd, p);
    }

    // 6. LN2 + SSF -> bf16
    ln_ssf_kernel<<<ROWS, 256>>>(px1, norm2_w, norm2_b, ssf_scale_2, ssf_shift_2, ph);

    // 7. fc1 GEMM + GELU -> bf16
    {
        EpiP p = {};
        p.bias = b_fc1; p.outb = pm;
        gemm_mma<2,128><<<dim3(MLPD/128, MT_), 256, GEMM_SMEM>>>(ph, pw1, ROWS, MLPD, Dd, p);
    }

    // 8. fc2 GEMM + SSF + gamma2 residual -> out (fp32)
    {
        EpiP p = {};
        p.bias = b_fc2; p.scale = ssf_scale_mlp; p.shift = ssf_shift_mlp;
        p.resid = px1; p.gamma = gamma_2; p.out = out;
        gemm_mma<3,128><<<dim3(Dd/128, MT_), 256, GEMM_SMEM>>>(pm, pw2, ROWS, Dd, MLPD, p);
    }
}

// round 8
// speedup vs baseline: 4.0392x; 1.1773x over previous
#include <cuda_runtime.h>
#include <cuda_bf16.h>
#include <math.h>
#include <stdint.h>

// ---------------- problem constants ----------------
#define Bb   64
#define Nn   197
#define Dd   768
#define Hh   12
#define HD   64
#define MLPD 3072
#define ROWS (Bb*Nn)          // 12608
#define LP   224              // padded l-stride

typedef __nv_bfloat16 bf16;
typedef __nv_bfloat162 bf162;

// ---------------- scratch (static device globals; no allocation) ----------------
__device__ __align__(16) bf16  g_h [ (size_t)ROWS * Dd ];
__device__ __align__(16) bf16  g_q [ (size_t)Bb * Hh * Nn * HD ];     // bf16, pre-scaled
__device__ __align__(16) bf16  g_k [ (size_t)Bb * Hh * Nn * HD ];
__device__ __align__(16) bf16  g_vt[ (size_t)Bb * Hh * HD * LP ];     // V^T (pads stay 0)
__device__ __align__(16) bf16  g_attn[ (size_t)Bb * Hh * Nn * LP ];   // softmax bf16 (pads 0)
__device__ __align__(16) bf16  g_mix [ (size_t)Bb * Hh * Nn * LP ];
__device__ __align__(16) bf16  g_y [ (size_t)ROWS * Dd ];
__device__ float g_x1[ (size_t)ROWS * Dd ];
__device__ __align__(16) bf16  g_m [ (size_t)ROWS * MLPD ];
__device__ float g_bias[ (size_t)Hh * Nn * 200 ];                     // per-head bias planes
// bf16 weight copies
__device__ __align__(16) bf16 g_wq[ (size_t)3 * Dd * Dd ];
__device__ __align__(16) bf16 g_wp[ (size_t)Dd * Dd ];
__device__ __align__(16) bf16 g_w1[ (size_t)MLPD * Dd ];
__device__ __align__(16) bf16 g_w2[ (size_t)Dd * MLPD ];

// ---------------- PTX helpers ----------------
__device__ __forceinline__ uint32_t smem_u32(const void* p) {
    uint32_t a;
    asm("{ .reg .u64 t; cvta.to.shared.u64 t, %1; cvt.u32.u64 %0, t; }" : "=r"(a) : "l"(p));
    return a;
}
__device__ __forceinline__ void cp16(uint32_t dst, const void* src) {
    asm volatile("cp.async.cg.shared.global [%0], [%1], 16;" :: "r"(dst), "l"(src));
}
__device__ __forceinline__ void sts_zero16(uint32_t dst) {
    asm volatile("st.shared.v4.b32 [%0], {%1,%1,%1,%1};" :: "r"(dst), "r"(0u));
}
__device__ __forceinline__ void cp_commit() { asm volatile("cp.async.commit_group;" ::: "memory"); }
template<int N>
__device__ __forceinline__ void cp_wait() { asm volatile("cp.async.wait_group %0;" :: "n"(N) : "memory"); }

__device__ __forceinline__ void ldsm4(uint32_t& r0, uint32_t& r1, uint32_t& r2, uint32_t& r3,
                                      uint32_t addr) {
    asm volatile("ldmatrix.sync.aligned.m8n8.x4.shared.b16 {%0,%1,%2,%3}, [%4];"
        : "=r"(r0), "=r"(r1), "=r"(r2), "=r"(r3) : "r"(addr));
}

// bf16 warp MMA: D(16x8) += A(16x16) * B(16x8)   [row.col]
__device__ __forceinline__ void mma_bf16(float* c, const uint32_t* a, const uint32_t* b) {
    asm volatile(
        "mma.sync.aligned.m16n8k16.row.col.f32.bf16.bf16.f32 "
        "{%0,%1,%2,%3}, {%4,%5,%6,%7}, {%8,%9}, {%0,%1,%2,%3};"
        : "+f"(c[0]), "+f"(c[1]), "+f"(c[2]), "+f"(c[3])
        : "r"(a[0]), "r"(a[1]), "r"(a[2]), "r"(a[3]), "r"(b[0]), "r"(b[1]));
}

// ---------------- epilogue params ----------------
struct EpiP {
    const float* bias;
    const float* scale;
    const float* shift;
    const float* resid;
    const float* gamma;
    float* out;      // fp32 outs: x1 (EPI1), final (EPI3)
    bf16*  outb;     // bf16 outs: gelu (EPI2), AV y (EPI4)
    bf16*  outq;     // EPI0
    bf16*  outk;     // EPI0
    bf16*  outv;     // EPI0 (VT)
    const float* qb;
    const float* vb;
};

// EPI: 0=qkv scatter, 1=proj(+resid,g1), 2=gelu, 3=fc2(+resid,g2), 4=AV out
template<int EPI>
__device__ __forceinline__ void epi_store(int r, int c, float a, int N_, const EpiP& p, int z) {
    if constexpr (EPI == 0) {
        int part = c / Dd;
        int rr = c - part * Dd;
        float bias = (part == 0) ? p.qb[rr] : (part == 2 ? p.vb[rr] : 0.f);
        float val = (a + bias) * p.scale[c] + p.shift[c];
        int b_ = r / Nn, n_ = r - b_ * Nn;
        int hh = rr >> 6, d = rr & 63;
        if (part == 0)
            p.outq[((((size_t)b_ * Hh + hh) * Nn) + n_) * HD + d] = __float2bfloat16_rn(val * 0.125f);
        else if (part == 1)
            p.outk[((((size_t)b_ * Hh + hh) * Nn) + n_) * HD + d] = __float2bfloat16_rn(val);
        else
            p.outv[(((size_t)b_ * Hh + hh) * HD + d) * LP + n_] = __float2bfloat16_rn(val);
    } else if constexpr (EPI == 1 || EPI == 3) {
        float val = (a + p.bias[c]) * p.scale[c] + p.shift[c];
        size_t idx = (size_t)r * N_ + c;
        p.out[idx] = p.resid[idx] + p.gamma[c] * val;
    } else if constexpr (EPI == 2) { // GELU -> bf16
        float v = a + p.bias[c];
        size_t idx = (size_t)r * N_ + c;
        p.outb[idx] = __float2bfloat16_rn(0.5f * v * (1.f + erff(v * 0.70710678118654752f)));
    } else { // EPI == 4: AV out
        int bb = z / Hh, hk = z - bb * Hh;
        p.outb[((size_t)bb * Nn + r) * Dd + hk * HD + c] = __float2bfloat16_rn(a);
    }
}

// ---------------- mma.sync bf16 GEMM:  C[M,N_] = A[M,K] * B[N_,K]^T ----------------
// 128xBN tile, 8 warps, K-slab KS (64 or 32), 3-stage cp.async, ldmatrix.
#define GSTAGES 3

template<int EPI, int BN, int KS>
__global__ __launch_bounds__(256, 2) void gemm_mma(
    const bf16* __restrict__ A, const bf16* __restrict__ Bw,
    int M, int N_, int K, EpiP p)
{
    constexpr int WCOLS = BN / 32;
    constexpr int MT = WCOLS;
    constexpr int ROWB = (KS == 64) ? 144 : 80;      // padded row bytes
    constexpr int AREGB = 128 * ROWB;
    constexpr int STAGEB = 2 * AREGB;
    constexpr int NCP = KS / 8;                      // cp16 per row
    extern __shared__ char smc[];
    int tid = threadIdx.x;
    int row0 = blockIdx.y << 7, col0 = blockIdx.x * BN;
    int z = blockIdx.z;
    if constexpr (EPI == 4) {
        A  += (size_t)z * (Nn * LP);
        Bw += (size_t)z * (HD * LP);
    }
    int warp = tid >> 5, lane = tid & 31;
    int wm = warp / WCOLS, wn = warp % WCOLS;
    int g = lane >> 2, t = lane & 3;
    int q = lane >> 3, ri = lane & 7;

    bool isB = tid >= 128;
    int lr = tid & 127;
    bool lactive = isB ? (lr < BN) : true;
    bool lvalid = isB ? true : (row0 + lr < M);
    const bf16* gsrc = isB ? (Bw + (size_t)(col0 + lr) * K)
                           : (A  + (size_t)(row0 + lr) * K);
    uint32_t smbase = smem_u32(smc);
    uint32_t sdst = smbase + (uint32_t)((isB ? AREGB : 0) + lr * ROWB);

    auto load_slab = [&](int slab, int stage) {
        if (!lactive) return;
        uint32_t dst = sdst + (uint32_t)stage * STAGEB;
        const bf16* src = gsrc + slab * KS;
        if (lvalid) {
            #pragma unroll
            for (int j = 0; j < NCP; j++) cp16(dst + j * 16, src + j * 8);
        } else {
            #pragma unroll
            for (int j = 0; j < NCP; j++) sts_zero16(dst + j * 16);
        }
    };

    uint32_t a_base = smbase
        + (uint32_t)(wm * (MT * 16) * ROWB)
        + (uint32_t)(((q & 1) * 8 + ri) * ROWB + (q >> 1) * 16);
    uint32_t b_base = smbase + AREGB
        + (uint32_t)(wn * 32 * ROWB)
        + (uint32_t)(((q >> 1) * 8 + ri) * ROWB + (q & 1) * 16);

    float c[MT][4][4];
    #pragma unroll
    for (int i = 0; i < MT; i++)
        #pragma unroll
        for (int j = 0; j < 4; j++)
            { c[i][j][0] = 0.f; c[i][j][1] = 0.f; c[i][j][2] = 0.f; c[i][j][3] = 0.f; }

    const int nslab = K / KS;
    load_slab(0, 0); cp_commit();
    if (nslab > 1) load_slab(1, 1);
    cp_commit();

    for (int s = 0; s < nslab; s++) {
        cp_wait<1>();
        __syncthreads();
        if (s + 2 < nslab) load_slab(s + 2, (s + 2) % GSTAGES);
        cp_commit();

        uint32_t stg = (uint32_t)(s % GSTAGES) * STAGEB;
        #pragma unroll
        for (int kk = 0; kk < KS / 16; kk++) {
            uint32_t coff = stg + (uint32_t)kk * 32u;
            uint32_t af[MT][4];
            #pragma unroll
            for (int mt = 0; mt < MT; mt++)
                ldsm4(af[mt][0], af[mt][1], af[mt][2], af[mt][3],
                      a_base + coff + (uint32_t)(mt * 16 * ROWB));
            uint32_t bf[4][2];
            #pragma unroll
            for (int ntp = 0; ntp < 2; ntp++)
                ldsm4(bf[2*ntp][0], bf[2*ntp][1], bf[2*ntp+1][0], bf[2*ntp+1][1],
                      b_base + coff + (uint32_t)(ntp * 16 * ROWB));
            #pragma unroll
            for (int mt = 0; mt < MT; mt++)
                #pragma unroll
                for (int nt = 0; nt < 4; nt++)
                    mma_bf16(c[mt][nt], af[mt], bf[nt]);
        }
    }
    cp_wait<0>();

    #pragma unroll
    for (int mt = 0; mt < MT; mt++) {
        int r_lo = row0 + wm * (MT * 16) + mt * 16 + g;
        int r_hi = r_lo + 8;
        #pragma unroll
        for (int nt = 0; nt < 4; nt++) {
            int cc = col0 + wn * 32 + nt * 8 + t * 2;
            if (r_lo < M) {
                epi_store<EPI>(r_lo, cc,     c[mt][nt][0], N_, p, z);
                epi_store<EPI>(r_lo, cc + 1, c[mt][nt][1], N_, p, z);
            }
            if (r_hi < M) {
                epi_store<EPI>(r_hi, cc,     c[mt][nt][2], N_, p, z);
                epi_store<EPI>(r_hi, cc + 1, c[mt][nt][3], N_, p, z);
            }
        }
    }
}

// ---------------- fp32 -> bf16 weight conversion ----------------
__global__ __launch_bounds__(256) void cvt_bf16_kernel(const float* __restrict__ in,
                                                       bf16* __restrict__ out, int n4)
{
    int i = blockIdx.x * 256 + threadIdx.x;
    if (i < n4) {
        float4 v = ((const float4*)in)[i];
        ((bf162*)out)[i * 2]     = __float22bfloat162_rn(make_float2(v.x, v.y));
        ((bf162*)out)[i * 2 + 1] = __float22bfloat162_rn(make_float2(v.z, v.w));
    }
}

// ---------------- per-head bias plane precompute ----------------
__global__ __launch_bounds__(256) void bias_pre_kernel(
    const float* __restrict__ table, const int* __restrict__ relidx,
    float* __restrict__ outp)
{
    int i = blockIdx.x * 256 + threadIdx.x;
    if (i < Nn * Nn) {
        int idx = relidx[i];
        int n = i / Nn, m = i - n * Nn;
        #pragma unroll
        for (int h = 0; h < Hh; h++)
            outp[(size_t)h * (Nn * 200) + n * 200 + m] = table[idx * Hh + h];
    }
}

// ---------------- LayerNorm + SSF -> bf16 ----------------
__global__ __launch_bounds__(256) void ln_ssf_kernel(
    const float* __restrict__ x, const float* __restrict__ w, const float* __restrict__ b,
    const float* __restrict__ sc, const float* __restrict__ sh, bf16* __restrict__ out)
{
    int row = blockIdx.x;
    const float* xr = x + (size_t)row * Dd;
    bf16* orow = out + (size_t)row * Dd;
    int tid = threadIdx.x;
    float v0 = xr[tid], v1 = xr[tid + 256], v2 = xr[tid + 512];
    float s = v0 + v1 + v2;
    __shared__ float red[8];
    int lane = tid & 31, wp = tid >> 5;
    #pragma unroll
    for (int o = 16; o; o >>= 1) s += __shfl_xor_sync(~0u, s, o);
    if (!lane) red[wp] = s;
    __syncthreads();
    float tot = red[0]+red[1]+red[2]+red[3]+red[4]+red[5]+red[6]+red[7];
    float mean = tot * (1.f / 768.f);
    float d0 = v0 - mean, d1 = v1 - mean, d2 = v2 - mean;
    float vs = d0*d0 + d1*d1 + d2*d2;
    #pragma unroll
    for (int o = 16; o; o >>= 1) vs += __shfl_xor_sync(~0u, vs, o);
    __syncthreads();
    if (!lane) red[wp] = vs;
    __syncthreads();
    float var = (red[0]+red[1]+red[2]+red[3]+red[4]+red[5]+red[6]+red[7]) * (1.f / 768.f);
    float inv = rsqrtf(var + 1e-5f);
    orow[tid]       = __float2bfloat16_rn((d0*inv*w[tid]       + b[tid])       * sc[tid]       + sh[tid]);
    orow[tid + 256] = __float2bfloat16_rn((d1*inv*w[tid + 256] + b[tid + 256]) * sc[tid + 256] + sh[tid + 256]);
    orow[tid + 512] = __float2bfloat16_rn((d2*inv*w[tid + 512] + b[tid + 512]) * sc[tid + 512] + sh[tid + 512]);
}

// ---------------- attention: S = Q K^T + bias_h, softmax -> bf16 (block per (b,h)) ----------------
// Q,K smem 208x72 halves (144B rows); 13 m16 tiles round-robin over 8 warps.
#define ATTN_SMEM (2 * 208 * 144)   // 59904 B

__global__ __launch_bounds__(256, 1) void attn_mma_kernel(
    const bf16* __restrict__ q, const bf16* __restrict__ k,
    const float* __restrict__ biaspc, bf16* __restrict__ attn)
{
    extern __shared__ char smc[];
    uint32_t smb = smem_u32(smc);
    uint32_t qsm = smb, ksm = smb + 208 * 144;
    int bh = blockIdx.x;
    int h = bh % Hh;
    int tid = threadIdx.x;
    const char* qg = (const char*)(q + (size_t)bh * Nn * HD);
    const char* kg = (const char*)(k + (size_t)bh * Nn * HD);
    for (int idx = tid; idx < 197 * 8; idx += 256) {
        int row = idx >> 3, off = (idx & 7) * 16;
        cp16(qsm + row * 144 + off, qg + row * 128 + off);
        cp16(ksm + row * 144 + off, kg + row * 128 + off);
    }
    cp_commit(); cp_wait<0>();
    __syncthreads();

    int warp = tid >> 5, lane = tid & 31;
    int g = lane >> 2, t = lane & 3;
    int q2 = lane >> 3, ri = lane & 7;
    uint32_t a_off = (uint32_t)(((q2 & 1) * 8 + ri) * 144 + (q2 >> 1) * 16);
    uint32_t b_off = (uint32_t)(((q2 >> 1) * 8 + ri) * 144 + (q2 & 1) * 16);
    const float* pb = biaspc + (size_t)h * (Nn * 200);
    bf16* ab = attn + (size_t)bh * Nn * LP;

    for (int mt = warp; mt < 13; mt += 8) {
        float c[26][4];
        #pragma unroll
        for (int i = 0; i < 26; i++)
            { c[i][0] = 0.f; c[i][1] = 0.f; c[i][2] = 0.f; c[i][3] = 0.f; }
        #pragma unroll
        for (int kc = 0; kc < 4; kc++) {
            uint32_t coff = (uint32_t)kc * 32u;
            uint32_t af[4];
            ldsm4(af[0], af[1], af[2], af[3], qsm + a_off + coff + (uint32_t)(mt * 16 * 144));
            #pragma unroll
            for (int j = 0; j < 13; j++) {
                uint32_t b0, b1, b2, b3;
                ldsm4(b0, b1, b2, b3, ksm + b_off + coff + (uint32_t)(j * 16 * 144));
                uint32_t blo[2] = {b0, b1}, bhi[2] = {b2, b3};
                mma_bf16(c[2*j],   af, blo);
                mma_bf16(c[2*j+1], af, bhi);
            }
        }
        #pragma unroll
        for (int half = 0; half < 2; half++) {
            int r = mt * 16 + g + half * 8;
            if (r >= Nn) continue;
            // bias add + mask
            float mx = -1e30f;
            #pragma unroll
            for (int nt = 0; nt < 26; nt++) {
                int cc = nt * 8 + t * 2;
                float l0 = -1e30f, l1 = -1e30f;
                if (cc < Nn) {
                    float2 bv = *(const float2*)(pb + r * 200 + cc);
                    l0 = c[nt][half*2+0] + bv.x;
                    l1 = (cc + 1 < Nn) ? (c[nt][half*2+1] + bv.y) : -1e30f;
                }
                c[nt][half*2+0] = l0; c[nt][half*2+1] = l1;
                mx = fmaxf(mx, fmaxf(l0, l1));
            }
            mx = fmaxf(mx, __shfl_xor_sync(~0u, mx, 1));
            mx = fmaxf(mx, __shfl_xor_sync(~0u, mx, 2));
            float sum = 0.f;
            #pragma unroll
            for (int nt = 0; nt < 26; nt++) {
                int cc = nt * 8 + t * 2;
                float e0 = (cc < Nn)     ? __expf(c[nt][half*2+0] - mx) : 0.f;
                float e1 = (cc + 1 < Nn) ? __expf(c[nt][half*2+1] - mx) : 0.f;
                c[nt][half*2+0] = e0; c[nt][half*2+1] = e1;
                sum += e0 + e1;
            }
            sum += __shfl_xor_sync(~0u, sum, 1);
            sum += __shfl_xor_sync(~0u, sum, 2);
            float inv = 1.f / sum;
            #pragma unroll
            for (int nt = 0; nt < 26; nt++) {
                int cc = nt * 8 + t * 2;
                if (cc < Nn) {
                    bf162 pr = __float22bfloat162_rn(
                        make_float2(c[nt][half*2+0] * inv, c[nt][half*2+1] * inv));
                    *(bf162*)(ab + (size_t)r * LP + cc) = pr;
                }
            }
        }
    }
}

// ---------------- DCF head mix (bf16 in/out) ----------------
__global__ __launch_bounds__(256) void mix_kernel(
    const bf16* __restrict__ attn, const float* __restrict__ bases,
    bf16* __restrict__ outp)
{
    __shared__ uint32_t a_s[Hh][LP/2];
    __shared__ float c_s[Hh][Hh];
    int bn = blockIdx.x;
    int b = bn / Nn, n = bn - b * Nn;
    int tid = threadIdx.x;
    if (tid < 144) {
        int kk = tid / 12, hh = tid % 12;
        c_s[hh][kk] = bases[kk * Hh + hh] + (hh == kk ? 1.f : 0.f);
    }
    const uint32_t* af = (const uint32_t*)attn;
    uint32_t* of = (uint32_t*)outp;
    const int L2 = LP / 2;  // 112
    for (int i = tid; i < Hh * L2; i += 256) {
        int hh = i / L2, l2 = i - hh * L2;
        a_s[hh][l2] = af[(((size_t)b * Hh + hh) * Nn + n) * L2 + l2];
    }
    __syncthreads();
    for (int i = tid; i < Hh * L2; i += 256) {
        int kk = i / L2, l2 = i - kk * L2;
        float2 acc = make_float2(0.f, 0.f);
        #pragma unroll
        for (int hh = 0; hh < Hh; hh++) {
            float cv = c_s[hh][kk];
            bf162 av = *(const bf162*)&a_s[hh][l2];
            float2 fa = __bfloat1622float2(av);
            acc.x = fmaf(cv, fa.x, acc.x);
            acc.y = fmaf(cv, fa.y, acc.y);
        }
        bf162 pr = __float22bfloat162_rn(acc);
        of[(((size_t)b * Hh + kk) * Nn + n) * L2 + l2] = *(uint32_t*)&pr;
    }
}

// ---------------- launcher ----------------
extern "C" void kernel_launch(void* const* d_in, const int* in_sizes, int n_in,
                              void* d_out, int out_size)
{
    const float* x             = (const float*)d_in[0];
    const float* w_qkv         = (const float*)d_in[1];
    const float* q_bias        = (const float*)d_in[2];
    const float* v_bias        = (const float*)d_in[3];
    const float* ssf_scale_qkv = (const float*)d_in[4];
    const float* ssf_shift_qkv = (const float*)d_in[5];
    const float* rel_table     = (const float*)d_in[6];
    const float* bases_coeff   = (const float*)d_in[7];
    const float* w_proj        = (const float*)d_in[8];
    const float* b_proj        = (const float*)d_in[9];
    const float* ssf_scale_pr  = (const float*)d_in[10];
    const float* ssf_shift_pr  = (const float*)d_in[11];
    const float* norm1_w       = (const float*)d_in[12];
    const float* norm1_b       = (const float*)d_in[13];
    const float* norm2_w       = (const float*)d_in[14];
    const float* norm2_b       = (const float*)d_in[15];
    const float* ssf_scale_1   = (const float*)d_in[16];
    const float* ssf_shift_1   = (const float*)d_in[17];
    const float* ssf_scale_2   = (const float*)d_in[18];
    const float* ssf_shift_2   = (const float*)d_in[19];
    const float* w_fc1         = (const float*)d_in[20];
    const float* b_fc1         = (const float*)d_in[21];
    const float* w_fc2         = (const float*)d_in[22];
    const float* b_fc2         = (const float*)d_in[23];
    const float* ssf_scale_mlp = (const float*)d_in[24];
    const float* ssf_shift_mlp = (const float*)d_in[25];
    const float* gamma_1       = (const float*)d_in[26];
    const float* gamma_2       = (const float*)d_in[27];
    const int*   rel_pos_index = (const int*)d_in[28];
    float* out = (float*)d_out;

    bf16 *ph, *pq, *pk, *pvt, *pattn, *pmix, *py, *pm, *pwq, *pwp, *pw1, *pw2;
    float *px1, *pbias;
    cudaGetSymbolAddress((void**)&ph,    g_h);
    cudaGetSymbolAddress((void**)&pq,    g_q);
    cudaGetSymbolAddress((void**)&pk,    g_k);
    cudaGetSymbolAddress((void**)&pvt,   g_vt);
    cudaGetSymbolAddress((void**)&pattn, g_attn);
    cudaGetSymbolAddress((void**)&pmix,  g_mix);
    cudaGetSymbolAddress((void**)&py,    g_y);
    cudaGetSymbolAddress((void**)&px1,   g_x1);
    cudaGetSymbolAddress((void**)&pm,    g_m);
    cudaGetSymbolAddress((void**)&pbias, g_bias);
    cudaGetSymbolAddress((void**)&pwq,   g_wq);
    cudaGetSymbolAddress((void**)&pwp,   g_wp);
    cudaGetSymbolAddress((void**)&pw1,   g_w1);
    cudaGetSymbolAddress((void**)&pw2,   g_w2);

    const int SM64 = GSTAGES * 2 * 128 * 144;   // 110592
    const int SM32 = GSTAGES * 2 * 128 * 80;    // 61440
    cudaFuncSetAttribute(gemm_mma<0,128,64>, cudaFuncAttributeMaxDynamicSharedMemorySize, SM64);
    cudaFuncSetAttribute(gemm_mma<1,128,64>, cudaFuncAttributeMaxDynamicSharedMemorySize, SM64);
    cudaFuncSetAttribute(gemm_mma<2,128,64>, cudaFuncAttributeMaxDynamicSharedMemorySize, SM64);
    cudaFuncSetAttribute(gemm_mma<3,128,64>, cudaFuncAttributeMaxDynamicSharedMemorySize, SM64);
    cudaFuncSetAttribute(gemm_mma<4,64,32>,  cudaFuncAttributeMaxDynamicSharedMemorySize, SM32);
    cudaFuncSetAttribute(attn_mma_kernel,    cudaFuncAttributeMaxDynamicSharedMemorySize, ATTN_SMEM);

    const int MT_ = (ROWS + 127) / 128;   // 99

    // 0. weights -> bf16; bias planes
    cvt_bf16_kernel<<<(3*Dd*Dd/4 + 255)/256, 256>>>(w_qkv, pwq, 3*Dd*Dd/4);
    cvt_bf16_kernel<<<(Dd*Dd/4   + 255)/256, 256>>>(w_proj, pwp, Dd*Dd/4);
    cvt_bf16_kernel<<<(MLPD*Dd/4 + 255)/256, 256>>>(w_fc1, pw1, MLPD*Dd/4);
    cvt_bf16_kernel<<<(Dd*MLPD/4 + 255)/256, 256>>>(w_fc2, pw2, Dd*MLPD/4);
    bias_pre_kernel<<<(Nn*Nn + 255)/256, 256>>>(rel_table, rel_pos_index, pbias);

    // 1. LN1 + SSF -> bf16
    ln_ssf_kernel<<<ROWS, 256>>>(x, norm1_w, norm1_b, ssf_scale_1, ssf_shift_1, ph);

    // 2. QKV GEMM + bias + SSF + scatter (q,k bf16; v -> V^T bf16)
    {
        EpiP p = {};
        p.scale = ssf_scale_qkv; p.shift = ssf_shift_qkv;
        p.outq = pq; p.outk = pk; p.outv = pvt;
        p.qb = q_bias; p.vb = v_bias;
        gemm_mma<0,128,64><<<dim3(3*Dd/128, MT_), 256, SM64>>>(ph, pwq, ROWS, 3*Dd, Dd, p);
    }

    // 3. attention scores (bf16 mma) + bias + softmax -> bf16
    attn_mma_kernel<<<Bb * Hh, 256, ATTN_SMEM>>>(pq, pk, pbias, pattn);

    // 4a. DCF head mix -> bf16
    mix_kernel<<<ROWS, 256>>>(pattn, bases_coeff, pmix);

    // 4b. AV batched GEMM
    {
        EpiP p = {};
        p.outb = py;
        gemm_mma<4,64,32><<<dim3(1, 2, Bb*Hh), 256, SM32>>>(pmix, pvt, Nn, HD, LP, p);
    }

    // 5. proj GEMM + SSF + gamma1 residual (fp32 out)
    {
        EpiP p = {};
        p.bias = b_proj; p.scale = ssf_scale_pr; p.shift = ssf_shift_pr;
        p.resid = x; p.gamma = gamma_1; p.out = px1;
        gemm_mma<1,128,64><<<dim3(Dd/128, MT_), 256, SM64>>>(py, pwp, ROWS, Dd, Dd, p);
    }

    // 6. LN2 + SSF -> bf16
    ln_ssf_kernel<<<ROWS, 256>>>(px1, norm2_w, norm2_b, ssf_scale_2, ssf_shift_2, ph);

    // 7. fc1 GEMM + GELU -> bf16
    {
        EpiP p = {};
        p.bias = b_fc1; p.outb = pm;
        gemm_mma<2,128,64><<<dim3(MLPD/128, MT_), 256, SM64>>>(ph, pw1, ROWS, MLPD, Dd, p);
    }

    // 8. fc2 GEMM + SSF + gamma2 residual -> out (fp32)
    {
        EpiP p = {};
        p.bias = b_fc2; p.scale = ssf_scale_mlp; p.shift = ssf_shift_mlp;
        p.resid = px1; p.gamma = gamma_2; p.out = out;
        gemm_mma<3,128,64><<<dim3(Dd/128, MT_), 256, SM64>>>(pm, pw2, ROWS, Dd, MLPD, p);
    }
}

// round 9
// speedup vs baseline: 4.8161x; 1.1923x over previous
#include <cuda_runtime.h>
#include <cuda_bf16.h>
#include <math.h>
#include <stdint.h>

// ---------------- problem constants ----------------
#define Bb   64
#define Nn   197
#define Dd   768
#define Hh   12
#define HD   64
#define MLPD 3072
#define ROWS (Bb*Nn)          // 12608
#define LP   224              // padded l-stride

typedef __nv_bfloat16 bf16;
typedef __nv_bfloat162 bf162;

// ---------------- scratch (static device globals; no allocation) ----------------
__device__ __align__(16) bf16  g_h [ (size_t)ROWS * Dd ];
__device__ __align__(16) bf16  g_q [ (size_t)Bb * Hh * Nn * HD ];
__device__ __align__(16) bf16  g_k [ (size_t)Bb * Hh * Nn * HD ];
__device__ __align__(16) bf16  g_vt[ (size_t)Bb * Hh * HD * LP ];     // pads stay 0
__device__ __align__(16) bf16  g_attn[ (size_t)Bb * Hh * Nn * LP ];   // pads stay 0
__device__ __align__(16) bf16  g_mix [ (size_t)Bb * Hh * Nn * LP ];
__device__ __align__(16) bf16  g_y [ (size_t)ROWS * Dd ];
__device__ float g_x1[ (size_t)ROWS * Dd ];
__device__ __align__(16) bf16  g_m [ (size_t)ROWS * MLPD ];
__device__ float g_bias[ (size_t)Hh * Nn * 200 ];
// bf16 weight copies
__device__ __align__(16) bf16 g_wq[ (size_t)3 * Dd * Dd ];
__device__ __align__(16) bf16 g_wp[ (size_t)Dd * Dd ];
__device__ __align__(16) bf16 g_w1[ (size_t)MLPD * Dd ];
__device__ __align__(16) bf16 g_w2[ (size_t)Dd * MLPD ];

// ---------------- PTX helpers ----------------
__device__ __forceinline__ uint32_t smem_u32(const void* p) {
    uint32_t a;
    asm("{ .reg .u64 t; cvta.to.shared.u64 t, %1; cvt.u32.u64 %0, t; }" : "=r"(a) : "l"(p));
    return a;
}
__device__ __forceinline__ void cp16(uint32_t dst, const void* src) {
    asm volatile("cp.async.cg.shared.global [%0], [%1], 16;" :: "r"(dst), "l"(src));
}
__device__ __forceinline__ void sts_zero16(uint32_t dst) {
    asm volatile("st.shared.v4.b32 [%0], {%1,%1,%1,%1};" :: "r"(dst), "r"(0u));
}
__device__ __forceinline__ void cp_commit() { asm volatile("cp.async.commit_group;" ::: "memory"); }
template<int N>
__device__ __forceinline__ void cp_wait() { asm volatile("cp.async.wait_group %0;" :: "n"(N) : "memory"); }

__device__ __forceinline__ void ldsm4(uint32_t& r0, uint32_t& r1, uint32_t& r2, uint32_t& r3,
                                      uint32_t addr) {
    asm volatile("ldmatrix.sync.aligned.m8n8.x4.shared.b16 {%0,%1,%2,%3}, [%4];"
        : "=r"(r0), "=r"(r1), "=r"(r2), "=r"(r3) : "r"(addr));
}

// bf16 warp MMA: D(16x8) += A(16x16) * B(16x8)   [row.col]
__device__ __forceinline__ void mma_bf16(float* c, const uint32_t* a, const uint32_t* b) {
    asm volatile(
        "mma.sync.aligned.m16n8k16.row.col.f32.bf16.bf16.f32 "
        "{%0,%1,%2,%3}, {%4,%5,%6,%7}, {%8,%9}, {%0,%1,%2,%3};"
        : "+f"(c[0]), "+f"(c[1]), "+f"(c[2]), "+f"(c[3])
        : "r"(a[0]), "r"(a[1]), "r"(a[2]), "r"(a[3]), "r"(b[0]), "r"(b[1]));
}

// ---------------- epilogue params ----------------
struct EpiP {
    const float* bias;
    const float* scale;
    const float* shift;
    const float* resid;
    const float* gamma;
    float* out;
    bf16*  outb;
    bf16*  outq;
    bf16*  outk;
    bf16*  outv;
    const float* qb;
    const float* vb;
};

// EPI: 0=qkv scatter, 1=proj(+resid,g1), 2=gelu, 3=fc2(+resid,g2), 4=AV out
template<int EPI>
__device__ __forceinline__ void epi_store(int r, int c, float a, int N_, const EpiP& p, int z) {
    if constexpr (EPI == 0) {
        int part = c / Dd;
        int rr = c - part * Dd;
        float bias = (part == 0) ? p.qb[rr] : (part == 2 ? p.vb[rr] : 0.f);
        float val = (a + bias) * p.scale[c] + p.shift[c];
        int b_ = r / Nn, n_ = r - b_ * Nn;
        int hh = rr >> 6, d = rr & 63;
        if (part == 0)
            p.outq[((((size_t)b_ * Hh + hh) * Nn) + n_) * HD + d] = __float2bfloat16_rn(val * 0.125f);
        else if (part == 1)
            p.outk[((((size_t)b_ * Hh + hh) * Nn) + n_) * HD + d] = __float2bfloat16_rn(val);
        else
            p.outv[(((size_t)b_ * Hh + hh) * HD + d) * LP + n_] = __float2bfloat16_rn(val);
    } else if constexpr (EPI == 1 || EPI == 3) {
        float val = (a + p.bias[c]) * p.scale[c] + p.shift[c];
        size_t idx = (size_t)r * N_ + c;
        p.out[idx] = p.resid[idx] + p.gamma[c] * val;
    } else if constexpr (EPI == 2) {
        float v = a + p.bias[c];
        size_t idx = (size_t)r * N_ + c;
        p.outb[idx] = __float2bfloat16_rn(0.5f * v * (1.f + erff(v * 0.70710678118654752f)));
    } else {
        int bb = z / Hh, hk = z - bb * Hh;
        p.outb[((size_t)bb * Nn + r) * Dd + hk * HD + c] = __float2bfloat16_rn(a);
    }
}

// ---------------- mma.sync bf16 GEMM:  C[M,N_] = A[M,K] * B[N_,K]^T ----------------
// BMxBN tile, 8 warps, K-slab KS, 3-stage cp.async, ldmatrix fragments.
#define GSTAGES 3

template<int EPI, int BM, int BN, int KS>
__global__ __launch_bounds__(256, (BM == 256) ? 1 : 2) void gemm_mma(
    const bf16* __restrict__ A, const bf16* __restrict__ Bw,
    int M, int N_, int K, EpiP p)
{
    constexpr int WCOLS = (BM == 256) ? 2 : BN / 32;
    constexpr int WROWS = 8 / WCOLS;
    constexpr int WTM = BM / WROWS;       // warp tile M
    constexpr int WTN = BN / WCOLS;       // warp tile N
    constexpr int MT = WTM / 16;
    constexpr int NT = WTN / 8;
    constexpr int NTP = NT / 2;
    constexpr int ROWB = (KS == 64) ? 144 : 80;
    constexpr int AREGB = BM * ROWB;
    constexpr int STAGEB = (BM + BN) * ROWB;
    constexpr int NCP = KS / 8;                       // 16B chunks per row
    constexpr int CHUNKS = (BM + BN) * NCP;
    constexpr int CPT = CHUNKS / 256;                 // chunks per thread
    extern __shared__ char smc[];
    int tid = threadIdx.x;
    int row0 = blockIdx.y * BM, col0 = blockIdx.x * BN;
    int z = blockIdx.z;
    if constexpr (EPI == 4) {
        A  += (size_t)z * (Nn * LP);
        Bw += (size_t)z * (HD * LP);
    }
    int warp = tid >> 5, lane = tid & 31;
    int wm = warp / WCOLS, wn = warp % WCOLS;
    int g = lane >> 2, t = lane & 3;
    int q2 = lane >> 3, ri = lane & 7;

    uint32_t smbase = smem_u32(smc);

    auto load_slab = [&](int slab, int stage) {
        uint32_t stg = smbase + (uint32_t)stage * STAGEB;
        #pragma unroll
        for (int i = 0; i < CPT; i++) {
            int c = tid + i * 256;
            int r = c / NCP, j = c % NCP;
            if (r < BM) {
                uint32_t dst = stg + (uint32_t)(r * ROWB + j * 16);
                if (row0 + r < M)
                    cp16(dst, A + (size_t)(row0 + r) * K + slab * KS + j * 8);
                else
                    sts_zero16(dst);
            } else {
                int rb = r - BM;
                uint32_t dst = stg + (uint32_t)(AREGB + rb * ROWB + j * 16);
                cp16(dst, Bw + (size_t)(col0 + rb) * K + slab * KS + j * 8);
            }
        }
    };

    uint32_t a_base = smbase
        + (uint32_t)(wm * WTM * ROWB)
        + (uint32_t)(((q2 & 1) * 8 + ri) * ROWB + (q2 >> 1) * 16);
    uint32_t b_base = smbase + AREGB
        + (uint32_t)(wn * WTN * ROWB)
        + (uint32_t)(((q2 >> 1) * 8 + ri) * ROWB + (q2 & 1) * 16);

    float c[MT][NT][4];
    #pragma unroll
    for (int i = 0; i < MT; i++)
        #pragma unroll
        for (int j = 0; j < NT; j++)
            { c[i][j][0] = 0.f; c[i][j][1] = 0.f; c[i][j][2] = 0.f; c[i][j][3] = 0.f; }

    const int nslab = K / KS;
    load_slab(0, 0); cp_commit();
    if (nslab > 1) load_slab(1, 1);
    cp_commit();

    for (int s = 0; s < nslab; s++) {
        cp_wait<1>();
        __syncthreads();
        if (s + 2 < nslab) load_slab(s + 2, (s + 2) % GSTAGES);
        cp_commit();

        uint32_t stg = (uint32_t)(s % GSTAGES) * STAGEB;
        #pragma unroll
        for (int kk = 0; kk < KS / 16; kk++) {
            uint32_t coff = stg + (uint32_t)kk * 32u;
            uint32_t af[MT][4];
            #pragma unroll
            for (int mt = 0; mt < MT; mt++)
                ldsm4(af[mt][0], af[mt][1], af[mt][2], af[mt][3],
                      a_base + coff + (uint32_t)(mt * 16 * ROWB));
            uint32_t bf[NT][2];
            #pragma unroll
            for (int ntp = 0; ntp < NTP; ntp++)
                ldsm4(bf[2*ntp][0], bf[2*ntp][1], bf[2*ntp+1][0], bf[2*ntp+1][1],
                      b_base + coff + (uint32_t)(ntp * 16 * ROWB));
            #pragma unroll
            for (int mt = 0; mt < MT; mt++)
                #pragma unroll
                for (int nt = 0; nt < NT; nt++)
                    mma_bf16(c[mt][nt], af[mt], bf[nt]);
        }
    }
    cp_wait<0>();

    #pragma unroll
    for (int mt = 0; mt < MT; mt++) {
        int r_lo = row0 + wm * WTM + mt * 16 + g;
        int r_hi = r_lo + 8;
        #pragma unroll
        for (int nt = 0; nt < NT; nt++) {
            int cc = col0 + wn * WTN + nt * 8 + t * 2;
            if (r_lo < M) {
                epi_store<EPI>(r_lo, cc,     c[mt][nt][0], N_, p, z);
                epi_store<EPI>(r_lo, cc + 1, c[mt][nt][1], N_, p, z);
            }
            if (r_hi < M) {
                epi_store<EPI>(r_hi, cc,     c[mt][nt][2], N_, p, z);
                epi_store<EPI>(r_hi, cc + 1, c[mt][nt][3], N_, p, z);
            }
        }
    }
}

// ---------------- fp32 -> bf16 weight conversion ----------------
__global__ __launch_bounds__(256) void cvt_bf16_kernel(const float* __restrict__ in,
                                                       bf16* __restrict__ out, int n4)
{
    int i = blockIdx.x * 256 + threadIdx.x;
    if (i < n4) {
        float4 v = ((const float4*)in)[i];
        ((bf162*)out)[i * 2]     = __float22bfloat162_rn(make_float2(v.x, v.y));
        ((bf162*)out)[i * 2 + 1] = __float22bfloat162_rn(make_float2(v.z, v.w));
    }
}

// ---------------- per-head bias plane precompute ----------------
__global__ __launch_bounds__(256) void bias_pre_kernel(
    const float* __restrict__ table, const int* __restrict__ relidx,
    float* __restrict__ outp)
{
    int i = blockIdx.x * 256 + threadIdx.x;
    if (i < Nn * Nn) {
        int idx = relidx[i];
        int n = i / Nn, m = i - n * Nn;
        #pragma unroll
        for (int h = 0; h < Hh; h++)
            outp[(size_t)h * (Nn * 200) + n * 200 + m] = table[idx * Hh + h];
    }
}

// ---------------- LayerNorm + SSF -> bf16 ----------------
__global__ __launch_bounds__(256) void ln_ssf_kernel(
    const float* __restrict__ x, const float* __restrict__ w, const float* __restrict__ b,
    const float* __restrict__ sc, const float* __restrict__ sh, bf16* __restrict__ out)
{
    int row = blockIdx.x;
    const float* xr = x + (size_t)row * Dd;
    bf16* orow = out + (size_t)row * Dd;
    int tid = threadIdx.x;
    float v0 = xr[tid], v1 = xr[tid + 256], v2 = xr[tid + 512];
    float s = v0 + v1 + v2;
    __shared__ float red[8];
    int lane = tid & 31, wp = tid >> 5;
    #pragma unroll
    for (int o = 16; o; o >>= 1) s += __shfl_xor_sync(~0u, s, o);
    if (!lane) red[wp] = s;
    __syncthreads();
    float tot = red[0]+red[1]+red[2]+red[3]+red[4]+red[5]+red[6]+red[7];
    float mean = tot * (1.f / 768.f);
    float d0 = v0 - mean, d1 = v1 - mean, d2 = v2 - mean;
    float vs = d0*d0 + d1*d1 + d2*d2;
    #pragma unroll
    for (int o = 16; o; o >>= 1) vs += __shfl_xor_sync(~0u, vs, o);
    __syncthreads();
    if (!lane) red[wp] = vs;
    __syncthreads();
    float var = (red[0]+red[1]+red[2]+red[3]+red[4]+red[5]+red[6]+red[7]) * (1.f / 768.f);
    float inv = rsqrtf(var + 1e-5f);
    orow[tid]       = __float2bfloat16_rn((d0*inv*w[tid]       + b[tid])       * sc[tid]       + sh[tid]);
    orow[tid + 256] = __float2bfloat16_rn((d1*inv*w[tid + 256] + b[tid + 256]) * sc[tid + 256] + sh[tid + 256]);
    orow[tid + 512] = __float2bfloat16_rn((d2*inv*w[tid + 512] + b[tid + 512]) * sc[tid + 512] + sh[tid + 512]);
}

// ---------------- attention: S = Q K^T + bias_h, softmax -> bf16 (block per (b,h)) ----------------
#define ATTN_SMEM (2 * 208 * 144)   // 59904 B

__global__ __launch_bounds__(256, 1) void attn_mma_kernel(
    const bf16* __restrict__ q, const bf16* __restrict__ k,
    const float* __restrict__ biaspc, bf16* __restrict__ attn)
{
    extern __shared__ char smc[];
    uint32_t smb = smem_u32(smc);
    uint32_t qsm = smb, ksm = smb + 208 * 144;
    int bh = blockIdx.x;
    int h = bh % Hh;
    int tid = threadIdx.x;
    const char* qg = (const char*)(q + (size_t)bh * Nn * HD);
    const char* kg = (const char*)(k + (size_t)bh * Nn * HD);
    for (int idx = tid; idx < 197 * 8; idx += 256) {
        int row = idx >> 3, off = (idx & 7) * 16;
        cp16(qsm + row * 144 + off, qg + row * 128 + off);
        cp16(ksm + row * 144 + off, kg + row * 128 + off);
    }
    cp_commit(); cp_wait<0>();
    __syncthreads();

    int warp = tid >> 5, lane = tid & 31;
    int g = lane >> 2, t = lane & 3;
    int q2 = lane >> 3, ri = lane & 7;
    uint32_t a_off = (uint32_t)(((q2 & 1) * 8 + ri) * 144 + (q2 >> 1) * 16);
    uint32_t b_off = (uint32_t)(((q2 >> 1) * 8 + ri) * 144 + (q2 & 1) * 16);
    const float* pb = biaspc + (size_t)h * (Nn * 200);
    bf16* ab = attn + (size_t)bh * Nn * LP;

    for (int mt = warp; mt < 13; mt += 8) {
        float c[26][4];
        #pragma unroll
        for (int i = 0; i < 26; i++)
            { c[i][0] = 0.f; c[i][1] = 0.f; c[i][2] = 0.f; c[i][3] = 0.f; }
        #pragma unroll
        for (int kc = 0; kc < 4; kc++) {
            uint32_t coff = (uint32_t)kc * 32u;
            uint32_t af[4];
            ldsm4(af[0], af[1], af[2], af[3], qsm + a_off + coff + (uint32_t)(mt * 16 * 144));
            #pragma unroll
            for (int j = 0; j < 13; j++) {
                uint32_t b0, b1, b2, b3;
                ldsm4(b0, b1, b2, b3, ksm + b_off + coff + (uint32_t)(j * 16 * 144));
                uint32_t blo[2] = {b0, b1}, bhi[2] = {b2, b3};
                mma_bf16(c[2*j],   af, blo);
                mma_bf16(c[2*j+1], af, bhi);
            }
        }
        #pragma unroll
        for (int half = 0; half < 2; half++) {
            int r = mt * 16 + g + half * 8;
            if (r >= Nn) continue;
            float mx = -1e30f;
            #pragma unroll
            for (int nt = 0; nt < 26; nt++) {
                int cc = nt * 8 + t * 2;
                float l0 = -1e30f, l1 = -1e30f;
                if (cc < Nn) {
                    float2 bv = *(const float2*)(pb + r * 200 + cc);
                    l0 = c[nt][half*2+0] + bv.x;
                    l1 = (cc + 1 < Nn) ? (c[nt][half*2+1] + bv.y) : -1e30f;
                }
                c[nt][half*2+0] = l0; c[nt][half*2+1] = l1;
                mx = fmaxf(mx, fmaxf(l0, l1));
            }
            mx = fmaxf(mx, __shfl_xor_sync(~0u, mx, 1));
            mx = fmaxf(mx, __shfl_xor_sync(~0u, mx, 2));
            float sum = 0.f;
            #pragma unroll
            for (int nt = 0; nt < 26; nt++) {
                int cc = nt * 8 + t * 2;
                float e0 = (cc < Nn)     ? __expf(c[nt][half*2+0] - mx) : 0.f;
                float e1 = (cc + 1 < Nn) ? __expf(c[nt][half*2+1] - mx) : 0.f;
                c[nt][half*2+0] = e0; c[nt][half*2+1] = e1;
                sum += e0 + e1;
            }
            sum += __shfl_xor_sync(~0u, sum, 1);
            sum += __shfl_xor_sync(~0u, sum, 2);
            float inv = 1.f / sum;
            #pragma unroll
            for (int nt = 0; nt < 26; nt++) {
                int cc = nt * 8 + t * 2;
                if (cc < Nn) {
                    bf162 pr = __float22bfloat162_rn(
                        make_float2(c[nt][half*2+0] * inv, c[nt][half*2+1] * inv));
                    *(bf162*)(ab + (size_t)r * LP + cc) = pr;
                }
            }
        }
    }
}

// ---------------- DCF head mix (bf16 in/out) ----------------
__global__ __launch_bounds__(256) void mix_kernel(
    const bf16* __restrict__ attn, const float* __restrict__ bases,
    bf16* __restrict__ outp)
{
    __shared__ uint32_t a_s[Hh][LP/2];
    __shared__ float c_s[Hh][Hh];
    int bn = blockIdx.x;
    int b = bn / Nn, n = bn - b * Nn;
    int tid = threadIdx.x;
    if (tid < 144) {
        int kk = tid / 12, hh = tid % 12;
        c_s[hh][kk] = bases[kk * Hh + hh] + (hh == kk ? 1.f : 0.f);
    }
    const uint32_t* af = (const uint32_t*)attn;
    uint32_t* of = (uint32_t*)outp;
    const int L2 = LP / 2;  // 112
    for (int i = tid; i < Hh * L2; i += 256) {
        int hh = i / L2, l2 = i - hh * L2;
        a_s[hh][l2] = af[(((size_t)b * Hh + hh) * Nn + n) * L2 + l2];
    }
    __syncthreads();
    for (int i = tid; i < Hh * L2; i += 256) {
        int kk = i / L2, l2 = i - kk * L2;
        float2 acc = make_float2(0.f, 0.f);
        #pragma unroll
        for (int hh = 0; hh < Hh; hh++) {
            float cv = c_s[hh][kk];
            bf162 av = *(const bf162*)&a_s[hh][l2];
            float2 fa = __bfloat1622float2(av);
            acc.x = fmaf(cv, fa.x, acc.x);
            acc.y = fmaf(cv, fa.y, acc.y);
        }
        bf162 pr = __float22bfloat162_rn(acc);
        of[(((size_t)b * Hh + kk) * Nn + n) * L2 + l2] = *(uint32_t*)&pr;
    }
}

// ---------------- launcher ----------------
extern "C" void kernel_launch(void* const* d_in, const int* in_sizes, int n_in,
                              void* d_out, int out_size)
{
    const float* x             = (const float*)d_in[0];
    const float* w_qkv         = (const float*)d_in[1];
    const float* q_bias        = (const float*)d_in[2];
    const float* v_bias        = (const float*)d_in[3];
    const float* ssf_scale_qkv = (const float*)d_in[4];
    const float* ssf_shift_qkv = (const float*)d_in[5];
    const float* rel_table     = (const float*)d_in[6];
    const float* bases_coeff   = (const float*)d_in[7];
    const float* w_proj        = (const float*)d_in[8];
    const float* b_proj        = (const float*)d_in[9];
    const float* ssf_scale_pr  = (const float*)d_in[10];
    const float* ssf_shift_pr  = (const float*)d_in[11];
    const float* norm1_w       = (const float*)d_in[12];
    const float* norm1_b       = (const float*)d_in[13];
    const float* norm2_w       = (const float*)d_in[14];
    const float* norm2_b       = (const float*)d_in[15];
    const float* ssf_scale_1   = (const float*)d_in[16];
    const float* ssf_shift_1   = (const float*)d_in[17];
    const float* ssf_scale_2   = (const float*)d_in[18];
    const float* ssf_shift_2   = (const float*)d_in[19];
    const float* w_fc1         = (const float*)d_in[20];
    const float* b_fc1         = (const float*)d_in[21];
    const float* w_fc2         = (const float*)d_in[22];
    const float* b_fc2         = (const float*)d_in[23];
    const float* ssf_scale_mlp = (const float*)d_in[24];
    const float* ssf_shift_mlp = (const float*)d_in[25];
    const float* gamma_1       = (const float*)d_in[26];
    const float* gamma_2       = (const float*)d_in[27];
    const int*   rel_pos_index = (const int*)d_in[28];
    float* out = (float*)d_out;

    bf16 *ph, *pq, *pk, *pvt, *pattn, *pmix, *py, *pm, *pwq, *pwp, *pw1, *pw2;
    float *px1, *pbias;
    cudaGetSymbolAddress((void**)&ph,    g_h);
    cudaGetSymbolAddress((void**)&pq,    g_q);
    cudaGetSymbolAddress((void**)&pk,    g_k);
    cudaGetSymbolAddress((void**)&pvt,   g_vt);
    cudaGetSymbolAddress((void**)&pattn, g_attn);
    cudaGetSymbolAddress((void**)&pmix,  g_mix);
    cudaGetSymbolAddress((void**)&py,    g_y);
    cudaGetSymbolAddress((void**)&px1,   g_x1);
    cudaGetSymbolAddress((void**)&pm,    g_m);
    cudaGetSymbolAddress((void**)&pbias, g_bias);
    cudaGetSymbolAddress((void**)&pwq,   g_wq);
    cudaGetSymbolAddress((void**)&pwp,   g_wp);
    cudaGetSymbolAddress((void**)&pw1,   g_w1);
    cudaGetSymbolAddress((void**)&pw2,   g_w2);

    const int SMBIG = GSTAGES * (256 + 128) * 144;   // 165888
    const int SMAV  = GSTAGES * (128 + 64) * 80;     // 46080
    cudaFuncSetAttribute(gemm_mma<0,256,128,64>, cudaFuncAttributeMaxDynamicSharedMemorySize, SMBIG);
    cudaFuncSetAttribute(gemm_mma<1,256,128,64>, cudaFuncAttributeMaxDynamicSharedMemorySize, SMBIG);
    cudaFuncSetAttribute(gemm_mma<2,256,128,64>, cudaFuncAttributeMaxDynamicSharedMemorySize, SMBIG);
    cudaFuncSetAttribute(gemm_mma<3,256,128,64>, cudaFuncAttributeMaxDynamicSharedMemorySize, SMBIG);
    cudaFuncSetAttribute(gemm_mma<4,128,64,32>,  cudaFuncAttributeMaxDynamicSharedMemorySize, SMAV);
    cudaFuncSetAttribute(attn_mma_kernel,        cudaFuncAttributeMaxDynamicSharedMemorySize, ATTN_SMEM);

    const int MT256 = (ROWS + 255) / 256;   // 50

    // 0. weights -> bf16; bias planes
    cvt_bf16_kernel<<<(3*Dd*Dd/4 + 255)/256, 256>>>(w_qkv, pwq, 3*Dd*Dd/4);
    cvt_bf16_kernel<<<(Dd*Dd/4   + 255)/256, 256>>>(w_proj, pwp, Dd*Dd/4);
    cvt_bf16_kernel<<<(MLPD*Dd/4 + 255)/256, 256>>>(w_fc1, pw1, MLPD*Dd/4);
    cvt_bf16_kernel<<<(Dd*MLPD/4 + 255)/256, 256>>>(w_fc2, pw2, Dd*MLPD/4);
    bias_pre_kernel<<<(Nn*Nn + 255)/256, 256>>>(rel_table, rel_pos_index, pbias);

    // 1. LN1 + SSF -> bf16
    ln_ssf_kernel<<<ROWS, 256>>>(x, norm1_w, norm1_b, ssf_scale_1, ssf_shift_1, ph);

    // 2. QKV GEMM + bias + SSF + scatter
    {
        EpiP p = {};
        p.scale = ssf_scale_qkv; p.shift = ssf_shift_qkv;
        p.outq = pq; p.outk = pk; p.outv = pvt;
        p.qb = q_bias; p.vb = v_bias;
        gemm_mma<0,256,128,64><<<dim3(3*Dd/128, MT256), 256, SMBIG>>>(ph, pwq, ROWS, 3*Dd, Dd, p);
    }

    // 3. attention scores (bf16 mma) + bias + softmax -> bf16
    attn_mma_kernel<<<Bb * Hh, 256, ATTN_SMEM>>>(pq, pk, pbias, pattn);

    // 4a. DCF head mix -> bf16
    mix_kernel<<<ROWS, 256>>>(pattn, bases_coeff, pmix);

    // 4b. AV batched GEMM
    {
        EpiP p = {};
        p.outb = py;
        gemm_mma<4,128,64,32><<<dim3(1, 2, Bb*Hh), 256, SMAV>>>(pmix, pvt, Nn, HD, LP, p);
    }

    // 5. proj GEMM + SSF + gamma1 residual (fp32 out)
    {
        EpiP p = {};
        p.bias = b_proj; p.scale = ssf_scale_pr; p.shift = ssf_shift_pr;
        p.resid = x; p.gamma = gamma_1; p.out = px1;
        gemm_mma<1,256,128,64><<<dim3(Dd/128, MT256), 256, SMBIG>>>(py, pwp, ROWS, Dd, Dd, p);
    }

    // 6. LN2 + SSF -> bf16
    ln_ssf_kernel<<<ROWS, 256>>>(px1, norm2_w, norm2_b, ssf_scale_2, ssf_shift_2, ph);

    // 7. fc1 GEMM + GELU -> bf16
    {
        EpiP p = {};
        p.bias = b_fc1; p.outb = pm;
        gemm_mma<2,256,128,64><<<dim3(MLPD/128, MT256), 256, SMBIG>>>(ph, pw1, ROWS, MLPD, Dd, p);
    }

    // 8. fc2 GEMM + SSF + gamma2 residual -> out (fp32)
    {
        EpiP p = {};
        p.bias = b_fc2; p.scale = ssf_scale_mlp; p.shift = ssf_shift_mlp;
        p.resid = px1; p.gamma = gamma_2; p.out = out;
        gemm_mma<3,256,128,64><<<dim3(Dd/128, MT256), 256, SMBIG>>>(pm, pw2, ROWS, Dd, MLPD, p);
    }
}